// round 2
// baseline (speedup 1.0000x reference)
#include <cuda_runtime.h>

#define NN 50000
#define NE 400000
#define NG 32
#define D  64
#define IND 11
#define EPSB 1e-5f

__device__ float g_h[NN*D];
__device__ float g_P[NN*D];
__device__ float g_Q[NN*D];
__device__ float g_y2[NE*D];
__device__ float g_aggr[NN*D];
__device__ float g_y3[NN*D];
__device__ float g_y4[NN*D];
__device__ float g_sum[D];
__device__ float g_sq[D];
__device__ float g_alpha[D];
__device__ float g_beta[D];
__device__ float g_gsum[NG*D];
__device__ float g_gcnt[NG];
__device__ int g_deg[NN];
__device__ int g_rowstart[NN+1];
__device__ int g_cursor[NN];
__device__ int g_eidx[NE];

// ---------- CSR build ----------
__global__ void k_zero() {
    int i = blockIdx.x*256 + threadIdx.x;
    if (i < NN) { g_deg[i] = 0; g_cursor[i] = 0; }
    if (i < D)  { g_sum[i] = 0.f; g_sq[i] = 0.f; }
    if (i < NG*D) g_gsum[i] = 0.f;
    if (i < NG)   g_gcnt[i] = 0.f;
}

__global__ void k_hist(const int* __restrict__ dst) {
    int e = blockIdx.x*256 + threadIdx.x;
    if (e < NE) atomicAdd(&g_deg[dst[e]], 1);
}

__global__ void k_scan() {
    __shared__ int wsum[32];
    __shared__ int carry;
    int t = threadIdx.x, lane = t & 31, w = t >> 5;
    if (t == 0) carry = 0;
    __syncthreads();
    for (int base = 0; base < NN; base += 1024) {
        int i = base + t;
        int v = (i < NN) ? g_deg[i] : 0;
        int x = v;
        for (int o = 1; o < 32; o <<= 1) { int y = __shfl_up_sync(~0u, x, o); if (lane >= o) x += y; }
        if (lane == 31) wsum[w] = x;
        __syncthreads();
        if (w == 0) {
            int s = wsum[lane];
            for (int o = 1; o < 32; o <<= 1) { int y = __shfl_up_sync(~0u, s, o); if (lane >= o) s += y; }
            wsum[lane] = s;
        }
        __syncthreads();
        int excl = carry + x - v + ((w > 0) ? wsum[w-1] : 0);
        if (i < NN) g_rowstart[i] = excl;
        __syncthreads();
        if (t == 0) carry += wsum[31];
        __syncthreads();
    }
    if (threadIdx.x == 0) g_rowstart[NN] = carry;
}

__global__ void k_scatter(const int* __restrict__ dst) {
    int e = blockIdx.x*256 + threadIdx.x;
    if (e < NE) {
        int d = dst[e];
        g_eidx[g_rowstart[d] + atomicAdd(&g_cursor[d], 1)] = e;
    }
}

__global__ void k_sortadj() {
    int n = blockIdx.x*128 + threadIdx.x;
    if (n >= NN) return;
    int s = g_rowstart[n], e = g_rowstart[n+1];
    for (int i = s+1; i < e; i++) {
        int key = g_eidx[i]; int j = i-1;
        while (j >= s && g_eidx[j] > key) { g_eidx[j+1] = g_eidx[j]; j--; }
        g_eidx[j+1] = key;
    }
}

// ---------- input projection ----------
__global__ void k_lin_in(const float* __restrict__ x, const float* __restrict__ W,
                         const float* __restrict__ b) {
    __shared__ float Ws[IND*D];
    __shared__ float bs[D];
    for (int i = threadIdx.x; i < IND*D; i += 256) Ws[i] = W[i];
    if (threadIdx.x < D) bs[threadIdx.x] = b[threadIdx.x];
    __syncthreads();
    int t = blockIdx.x*256 + threadIdx.x;
    int node = t >> 2, c0 = (t & 3) * 16;
    if (node >= NN) return;
    float xs[IND];
#pragma unroll
    for (int k = 0; k < IND; k++) xs[k] = x[node*IND + k];
#pragma unroll
    for (int j = 0; j < 16; j++) {
        int c = c0 + j;
        float acc = bs[c];
#pragma unroll
        for (int k = 0; k < IND; k++) acc = fmaf(xs[k], Ws[k*D + c], acc);
        g_h[node*D + c] = acc;
    }
}

// ---------- 128x64x64 GEMM core ----------
__device__ __forceinline__ void gemm_8x8(const float* __restrict__ As,
                                         const float* __restrict__ Ws,
                                         int e0, int j0, float acc[8][8]) {
#pragma unroll 8
    for (int k = 0; k < 64; k++) {
        float4 a0 = *(const float4*)(As + k*128 + e0);
        float4 a1 = *(const float4*)(As + k*128 + e0 + 4);
        float4 w0 = *(const float4*)(Ws + k*64 + j0);
        float4 w1 = *(const float4*)(Ws + k*64 + j0 + 4);
        float av[8] = {a0.x,a0.y,a0.z,a0.w,a1.x,a1.y,a1.z,a1.w};
        float wv[8] = {w0.x,w0.y,w0.z,w0.w,w1.x,w1.y,w1.z,w1.w};
#pragma unroll
        for (int i = 0; i < 8; i++)
#pragma unroll
            for (int j = 0; j < 8; j++)
                acc[i][j] = fmaf(av[i], wv[j], acc[i][j]);
    }
}

__device__ __forceinline__ void load_h_to_As(float* As, const float* srcbuf, int n, int t, bool valid) {
    if (valid) {
#pragma unroll
        for (int kb = 0; kb < 16; kb++) {
            float4 v = *(const float4*)(srcbuf + n*64 + kb*4);
            int c = kb*4;
            As[(c+0)*128+t] = v.x; As[(c+1)*128+t] = v.y;
            As[(c+2)*128+t] = v.z; As[(c+3)*128+t] = v.w;
        }
    } else {
#pragma unroll
        for (int k = 0; k < 64; k++) As[k*128+t] = 0.f;
    }
}

// ---------- P = h@Wd + b1, Q = h@Ws ----------
#define SM_PQ ((8192 + 4096 + 64) * 4)
__global__ void __launch_bounds__(128) k_nodePQ(const float* __restrict__ W1,
                                                const float* __restrict__ b1) {
    extern __shared__ float sm[];
    float* As = sm; float* Ws = sm + 8192; float* b1s = Ws + 4096;
    int t = threadIdx.x, base = blockIdx.x*128, n = base + t;
    load_h_to_As(As, g_h, n, t, n < NN);
    if (t < 64) b1s[t] = b1[t];
    for (int i = t; i < 4096; i += 128) Ws[i] = W1[i];
    __syncthreads();
    int e0 = (t >> 3) * 8, j0 = (t & 7) * 8;
    float acc[8][8];
#pragma unroll
    for (int i = 0; i < 8; i++)
#pragma unroll
        for (int j = 0; j < 8; j++) acc[i][j] = 0.f;
    gemm_8x8(As, Ws, e0, j0, acc);
#pragma unroll
    for (int i = 0; i < 8; i++) {
        int nn = base + e0 + i;
        if (nn < NN) {
            float4 o0 = {acc[i][0]+b1s[j0], acc[i][1]+b1s[j0+1], acc[i][2]+b1s[j0+2], acc[i][3]+b1s[j0+3]};
            float4 o1 = {acc[i][4]+b1s[j0+4], acc[i][5]+b1s[j0+5], acc[i][6]+b1s[j0+6], acc[i][7]+b1s[j0+7]};
            *(float4*)(g_P + nn*64 + j0) = o0;
            *(float4*)(g_P + nn*64 + j0 + 4) = o1;
        }
    }
    __syncthreads();
    for (int i = t; i < 4096; i += 128) Ws[i] = W1[4096 + i];
    __syncthreads();
#pragma unroll
    for (int i = 0; i < 8; i++)
#pragma unroll
        for (int j = 0; j < 8; j++) acc[i][j] = 0.f;
    gemm_8x8(As, Ws, e0, j0, acc);
#pragma unroll
    for (int i = 0; i < 8; i++) {
        int nn = base + e0 + i;
        if (nn < NN) {
            float4 o0 = {acc[i][0], acc[i][1], acc[i][2], acc[i][3]};
            float4 o1 = {acc[i][4], acc[i][5], acc[i][6], acc[i][7]};
            *(float4*)(g_Q + nn*64 + j0) = o0;
            *(float4*)(g_Q + nn*64 + j0 + 4) = o1;
        }
    }
}

// ---------- pass A: y1 stats ----------
__global__ void k_edgeA(const int* __restrict__ src, const int* __restrict__ dst,
                        const float* __restrict__ ea, const float* __restrict__ W1) {
    __shared__ float Weas[256];
    __shared__ float ssum[64], ssq[64];
    int t = threadIdx.x;
    for (int i = t; i < 256; i += 256) Weas[i] = W1[8192 + i];
    if (t < 64) { ssum[t] = 0.f; ssq[t] = 0.f; }
    __syncthreads();
    int wg = (blockIdx.x*256 + t) >> 5, lane = t & 31;
    int nw = (gridDim.x*256) >> 5;
    float s0 = 0.f, s1 = 0.f, q0 = 0.f, q1 = 0.f;
    for (int e = wg; e < NE; e += nw) {
        int s = src[e], d = dst[e];
        float4 ev = *(const float4*)(ea + e*4);
        int c = lane;
        float y = g_P[d*64+c] + g_Q[s*64+c]
                + ev.x*Weas[c] + ev.y*Weas[64+c] + ev.z*Weas[128+c] + ev.w*Weas[192+c];
        s0 += y; q0 += y*y;
        c = lane + 32;
        float z = g_P[d*64+c] + g_Q[s*64+c]
                + ev.x*Weas[c] + ev.y*Weas[64+c] + ev.z*Weas[128+c] + ev.w*Weas[192+c];
        s1 += z; q1 += z*z;
    }
    atomicAdd(&ssum[lane], s0); atomicAdd(&ssum[lane+32], s1);
    atomicAdd(&ssq[lane],  q0); atomicAdd(&ssq[lane+32],  q1);
    __syncthreads();
    if (t < 64) { atomicAdd(&g_sum[t], ssum[t]); atomicAdd(&g_sq[t], ssq[t]); }
}

// ---------- finalize BN ----------
__global__ void k_fin(float invn, const float* __restrict__ g, const float* __restrict__ be) {
    int c = threadIdx.x;
    float m = g_sum[c] * invn;
    float v = fmaxf(g_sq[c] * invn - m*m, 0.f);
    float a = g[c] * rsqrtf(v + EPSB);
    g_alpha[c] = a;
    g_beta[c]  = be[c] - a*m;
    g_sum[c] = 0.f; g_sq[c] = 0.f;
}

// ---------- pass B: bn1+relu, y2 = m1@W2+b2, stats2 ----------
#define SM_EB ((8192 + 4096 + 256 + 64 + 64 + 64 + 256 + 256) * 4)
__global__ void __launch_bounds__(128) k_edgeB(const int* __restrict__ src, const int* __restrict__ dst,
                                               const float* __restrict__ ea, const float* __restrict__ W1,
                                               const float* __restrict__ W2, const float* __restrict__ b2) {
    extern __shared__ float sm[];
    float* As = sm; float* Ws = As + 8192; float* Weas = Ws + 4096;
    float* al = Weas + 256; float* be = al + 64; float* b2s = be + 64;
    float* ssum = b2s + 64; float* ssq = ssum + 256;
    int t = threadIdx.x, base = blockIdx.x*128, e = base + t;
    for (int i = t; i < 4096; i += 128) Ws[i] = W2[i];
    for (int i = t; i < 256; i += 128) { Weas[i] = W1[8192 + i]; ssum[i] = 0.f; ssq[i] = 0.f; }
    if (t < 64) { al[t] = g_alpha[t]; be[t] = g_beta[t]; b2s[t] = b2[t]; }
    __syncthreads();
    int d0 = dst[e], s0 = src[e];
    float4 ev = *(const float4*)(ea + e*4);
    const float4* Pp = (const float4*)(g_P + d0*64);
    const float4* Qp = (const float4*)(g_Q + s0*64);
#pragma unroll
    for (int kb = 0; kb < 16; kb++) {
        float4 p = Pp[kb], q = Qp[kb];
        int c = kb*4;
#pragma unroll
        for (int u = 0; u < 4; u++) {
            float pv = (u==0)?p.x:(u==1)?p.y:(u==2)?p.z:p.w;
            float qv = (u==0)?q.x:(u==1)?q.y:(u==2)?q.z:q.w;
            int cc = c + u;
            float y = pv + qv + ev.x*Weas[cc] + ev.y*Weas[64+cc] + ev.z*Weas[128+cc] + ev.w*Weas[192+cc];
            As[cc*128+t] = fmaxf(fmaf(al[cc], y, be[cc]), 0.f);
        }
    }
    __syncthreads();
    int e0 = (t >> 3) * 8, j0 = (t & 7) * 8;
    float acc[8][8];
#pragma unroll
    for (int i = 0; i < 8; i++)
#pragma unroll
        for (int j = 0; j < 8; j++) acc[i][j] = 0.f;
    gemm_8x8(As, Ws, e0, j0, acc);
    float cs[8], cq[8];
#pragma unroll
    for (int j = 0; j < 8; j++) { cs[j] = 0.f; cq[j] = 0.f; }
#pragma unroll
    for (int i = 0; i < 8; i++) {
        float v[8];
#pragma unroll
        for (int j = 0; j < 8; j++) { v[j] = acc[i][j] + b2s[j0+j]; cs[j] += v[j]; cq[j] += v[j]*v[j]; }
        float4 o0 = {v[0],v[1],v[2],v[3]};
        float4 o1 = {v[4],v[5],v[6],v[7]};
        *(float4*)(g_y2 + (base+e0+i)*64 + j0) = o0;
        *(float4*)(g_y2 + (base+e0+i)*64 + j0 + 4) = o1;
    }
    int w = t >> 5;
#pragma unroll
    for (int j = 0; j < 8; j++) {
        atomicAdd(&ssum[w*64 + j0 + j], cs[j]);
        atomicAdd(&ssq [w*64 + j0 + j], cq[j]);
    }
    __syncthreads();
    if (t < 64) {
        atomicAdd(&g_sum[t], ssum[t]+ssum[64+t]+ssum[128+t]+ssum[192+t]);
        atomicAdd(&g_sq [t], ssq [t]+ssq [64+t]+ssq [128+t]+ssq [192+t]);
    }
}

// ---------- CSR aggregation (bn2+relu fused) ----------
__global__ void k_aggr() {
    int w = (blockIdx.x*256 + threadIdx.x) >> 5;
    if (w >= NN) return;
    int lane = threadIdx.x & 31;
    float al0 = g_alpha[lane],    be0 = g_beta[lane];
    float al1 = g_alpha[lane+32], be1 = g_beta[lane+32];
    float a0 = 0.f, a1 = 0.f;
    int s = g_rowstart[w], e = g_rowstart[w+1];
    for (int p = s; p < e; p++) {
        int eid = g_eidx[p];
        a0 += fmaxf(fmaf(al0, g_y2[eid*64 + lane],      be0), 0.f);
        a1 += fmaxf(fmaf(al1, g_y2[eid*64 + lane + 32], be1), 0.f);
    }
    g_aggr[w*64 + lane]      = a0;
    g_aggr[w*64 + lane + 32] = a1;
}

// ---------- node update 1: y3 = [h,aggr]@U1 + b3, stats ----------
#define SM_U1 ((8192 + 4096 + 64 + 256 + 256) * 4)
__global__ void __launch_bounds__(128) k_nodeU1(const float* __restrict__ W,
                                                const float* __restrict__ b3) {
    extern __shared__ float sm[];
    float* As = sm; float* Ws = As + 8192; float* b3s = Ws + 4096;
    float* ssum = b3s + 64; float* ssq = ssum + 256;
    int t = threadIdx.x, base = blockIdx.x*128, n = base + t;
    load_h_to_As(As, g_h, n, t, n < NN);
    for (int i = t; i < 4096; i += 128) Ws[i] = W[i];
    if (t < 64) b3s[t] = b3[t];
    for (int i = t; i < 256; i += 128) { ssum[i] = 0.f; ssq[i] = 0.f; }
    __syncthreads();
    int e0 = (t >> 3) * 8, j0 = (t & 7) * 8;
    float acc[8][8];
#pragma unroll
    for (int i = 0; i < 8; i++)
#pragma unroll
        for (int j = 0; j < 8; j++) acc[i][j] = 0.f;
    gemm_8x8(As, Ws, e0, j0, acc);
    __syncthreads();
    load_h_to_As(As, g_aggr, n, t, n < NN);
    for (int i = t; i < 4096; i += 128) Ws[i] = W[4096 + i];
    __syncthreads();
    gemm_8x8(As, Ws, e0, j0, acc);
    float cs[8], cq[8];
#pragma unroll
    for (int j = 0; j < 8; j++) { cs[j] = 0.f; cq[j] = 0.f; }
#pragma unroll
    for (int i = 0; i < 8; i++) {
        int n2 = base + e0 + i;
        if (n2 < NN) {
            float v[8];
#pragma unroll
            for (int j = 0; j < 8; j++) { v[j] = acc[i][j] + b3s[j0+j]; cs[j] += v[j]; cq[j] += v[j]*v[j]; }
            float4 o0 = {v[0],v[1],v[2],v[3]};
            float4 o1 = {v[4],v[5],v[6],v[7]};
            *(float4*)(g_y3 + n2*64 + j0) = o0;
            *(float4*)(g_y3 + n2*64 + j0 + 4) = o1;
        }
    }
    int w = t >> 5;
#pragma unroll
    for (int j = 0; j < 8; j++) {
        atomicAdd(&ssum[w*64 + j0 + j], cs[j]);
        atomicAdd(&ssq [w*64 + j0 + j], cq[j]);
    }
    __syncthreads();
    if (t < 64) {
        atomicAdd(&g_sum[t], ssum[t]+ssum[64+t]+ssum[128+t]+ssum[192+t]);
        atomicAdd(&g_sq [t], ssq [t]+ssq [64+t]+ssq [128+t]+ssq [192+t]);
    }
}

// ---------- node update 2: u1=relu(bn3(y3)); y4=u1@U2+b4, stats ----------
#define SM_U2 ((8192 + 4096 + 64 + 64 + 64 + 256 + 256) * 4)
__global__ void __launch_bounds__(128) k_nodeU2(const float* __restrict__ W,
                                                const float* __restrict__ b4) {
    extern __shared__ float sm[];
    float* As = sm; float* Ws = As + 8192; float* al = Ws + 4096;
    float* be = al + 64; float* b4s = be + 64;
    float* ssum = b4s + 64; float* ssq = ssum + 256;
    int t = threadIdx.x, base = blockIdx.x*128, n = base + t;
    for (int i = t; i < 4096; i += 128) Ws[i] = W[i];
    if (t < 64) { al[t] = g_alpha[t]; be[t] = g_beta[t]; b4s[t] = b4[t]; }
    for (int i = t; i < 256; i += 128) { ssum[i] = 0.f; ssq[i] = 0.f; }
    if (n < NN) {
#pragma unroll
        for (int kb = 0; kb < 16; kb++) {
            float4 v = *(const float4*)(g_y3 + n*64 + kb*4);
            int c = kb*4;
            As[(c+0)*128+t] = v.x; As[(c+1)*128+t] = v.y;
            As[(c+2)*128+t] = v.z; As[(c+3)*128+t] = v.w;
        }
    } else {
#pragma unroll
        for (int k = 0; k < 64; k++) As[k*128+t] = 0.f;
    }
    __syncthreads();
    // apply bn3+relu in place (each thread owns column t%64? no: redo per element)
    // As currently holds raw y3; transform: As[c*128+r] = relu(al[c]*y3+be[c])
    for (int i = t; i < 8192; i += 128) {
        int c = i >> 7;
        As[i] = fmaxf(fmaf(al[c], As[i], be[c]), 0.f);
    }
    __syncthreads();
    int e0 = (t >> 3) * 8, j0 = (t & 7) * 8;
    float acc[8][8];
#pragma unroll
    for (int i = 0; i < 8; i++)
#pragma unroll
        for (int j = 0; j < 8; j++) acc[i][j] = 0.f;
    gemm_8x8(As, Ws, e0, j0, acc);
    float cs[8], cq[8];
#pragma unroll
    for (int j = 0; j < 8; j++) { cs[j] = 0.f; cq[j] = 0.f; }
#pragma unroll
    for (int i = 0; i < 8; i++) {
        int n2 = base + e0 + i;
        if (n2 < NN) {
            float v[8];
#pragma unroll
            for (int j = 0; j < 8; j++) { v[j] = acc[i][j] + b4s[j0+j]; cs[j] += v[j]; cq[j] += v[j]*v[j]; }
            float4 o0 = {v[0],v[1],v[2],v[3]};
            float4 o1 = {v[4],v[5],v[6],v[7]};
            *(float4*)(g_y4 + n2*64 + j0) = o0;
            *(float4*)(g_y4 + n2*64 + j0 + 4) = o1;
        }
    }
    int w = t >> 5;
#pragma unroll
    for (int j = 0; j < 8; j++) {
        atomicAdd(&ssum[w*64 + j0 + j], cs[j]);
        atomicAdd(&ssq [w*64 + j0 + j], cq[j]);
    }
    __syncthreads();
    if (t < 64) {
        atomicAdd(&g_sum[t], ssum[t]+ssum[64+t]+ssum[128+t]+ssum[192+t]);
        atomicAdd(&g_sq [t], ssq [t]+ssq [64+t]+ssq [128+t]+ssq [192+t]);
    }
}

// ---------- residual ----------
__global__ void k_resid() {
    int i = blockIdx.x*256 + threadIdx.x;
    if (i < NN*D) {
        int c = i & 63;
        g_h[i] += fmaxf(fmaf(g_alpha[c], g_y4[i], g_beta[c]), 0.f);
    }
}

// ---------- pooling + prediction ----------
__global__ void k_pool(const int* __restrict__ batch) {
    int i = blockIdx.x*256 + threadIdx.x;
    if (i < NN*D) {
        int n = i >> 6, c = i & 63;
        int g = batch[n];
        atomicAdd(&g_gsum[g*64 + c], g_h[i]);
        if (c == 0) atomicAdd(&g_gcnt[g], 1.f);
    }
}

__global__ void k_pred(const float* __restrict__ pW, const float* __restrict__ pb,
                       float* __restrict__ out) {
    int g = threadIdx.x;
    if (g < NG) {
        float cnt = fmaxf(g_gcnt[g], 1.f);
        float acc = pb[0];
        for (int c = 0; c < D; c++) acc += g_gsum[g*64 + c] / cnt * pW[c];
        out[g] = acc;
    }
}

extern "C" void kernel_launch(void* const* d_in, const int* in_sizes, int n_in,
                              void* d_out, int out_size) {
    const float* x    = (const float*)d_in[0];
    const float* ea   = (const float*)d_in[1];
    const int*   ei   = (const int*)d_in[2];
    const int*   batch= (const int*)d_in[3];
    const float* linW = (const float*)d_in[4];
    const float* linb = (const float*)d_in[5];
    const float* mW1  = (const float*)d_in[6];
    const float* mb1  = (const float*)d_in[7];
    const float* mg1  = (const float*)d_in[8];
    const float* mbe1 = (const float*)d_in[9];
    const float* mW2  = (const float*)d_in[10];
    const float* mb2  = (const float*)d_in[11];
    const float* mg2  = (const float*)d_in[12];
    const float* mbe2 = (const float*)d_in[13];
    const float* uW1  = (const float*)d_in[14];
    const float* ub1  = (const float*)d_in[15];
    const float* ug1  = (const float*)d_in[16];
    const float* ube1 = (const float*)d_in[17];
    const float* uW2  = (const float*)d_in[18];
    const float* ub2  = (const float*)d_in[19];
    const float* ug2  = (const float*)d_in[20];
    const float* ube2 = (const float*)d_in[21];
    const float* pW   = (const float*)d_in[22];
    const float* pb   = (const float*)d_in[23];
    float* out = (float*)d_out;
    const int* src = ei;
    const int* dst = ei + NE;

    cudaFuncSetAttribute(k_nodePQ, cudaFuncAttributeMaxDynamicSharedMemorySize, SM_PQ);
    cudaFuncSetAttribute(k_edgeB,  cudaFuncAttributeMaxDynamicSharedMemorySize, SM_EB);
    cudaFuncSetAttribute(k_nodeU1, cudaFuncAttributeMaxDynamicSharedMemorySize, SM_U1);
    cudaFuncSetAttribute(k_nodeU2, cudaFuncAttributeMaxDynamicSharedMemorySize, SM_U2);

    k_zero<<<(NN+255)/256, 256>>>();
    k_hist<<<(NE+255)/256, 256>>>(dst);
    k_scan<<<1, 1024>>>();
    k_scatter<<<(NE+255)/256, 256>>>(dst);
    k_sortadj<<<(NN+127)/128, 128>>>();
    k_lin_in<<<(NN*4+255)/256, 256>>>(x, linW, linb);

    int nblk = (NN + 127) / 128;
    for (int l = 0; l < 4; l++) {
        const float* W1 = mW1 + l*132*64;
        k_nodePQ<<<nblk, 128, SM_PQ>>>(W1, mb1 + l*64);
        k_edgeA<<<512, 256>>>(src, dst, ea, W1);
        k_fin<<<1, 64>>>(1.f/NE, mg1 + l*64, mbe1 + l*64);
        k_edgeB<<<NE/128, 128, SM_EB>>>(src, dst, ea, W1, mW2 + l*4096, mb2 + l*64);
        k_fin<<<1, 64>>>(1.f/NE, mg2 + l*64, mbe2 + l*64);
        k_aggr<<<(NN*32+255)/256, 256>>>();
        k_nodeU1<<<nblk, 128, SM_U1>>>(uW1 + l*128*64, ub1 + l*64);
        k_fin<<<1, 64>>>(1.f/NN, ug1 + l*64, ube1 + l*64);
        k_nodeU2<<<nblk, 128, SM_U2>>>(uW2 + l*4096, ub2 + l*64);
        k_fin<<<1, 64>>>(1.f/NN, ug2 + l*64, ube2 + l*64);
        k_resid<<<(NN*D+255)/256, 256>>>();
    }
    k_pool<<<(NN*D+255)/256, 256>>>(batch);
    k_pred<<<1, 32>>>(pW, pb, out);
}

// round 3
// speedup vs baseline: 1.1013x; 1.1013x over previous
#include <cuda_runtime.h>
#include <cuda_bf16.h>

#define NN 50000
#define NE 400000
#define NG 32
#define D  64
#define IND 11
#define EPSB 1e-5f

__device__ float g_h[NN*D];
__device__ float g_P[NN*D];
__device__ float g_Q[NN*D];
__device__ __nv_bfloat16 g_y2[NE*D];
__device__ float g_aggr[NN*D];
__device__ float g_y3[NN*D];
__device__ float g_y4[NN*D];
__device__ float g_sum[16*64];   // [layer*4+stage][64]
__device__ float g_sq[16*64];
__device__ float g_gsum[NG*D];
__device__ float g_gcnt[NG];
__device__ int g_deg[NN];
__device__ int g_rowstart[NN+1];
__device__ int g_cursor[NN];
__device__ int g_eidx[NE];

// block-local BN finalize: threads t<64 fill al/be from stat slot
__device__ __forceinline__ void bnprep(float* al, float* bes, int slot, float invn,
                                       const float* __restrict__ g,
                                       const float* __restrict__ bb, int t) {
    if (t < 64) {
        float m = g_sum[slot*64+t] * invn;
        float v = fmaxf(g_sq[slot*64+t] * invn - m*m, 0.f);
        float a = g[t] * rsqrtf(v + EPSB);
        al[t] = a; bes[t] = bb[t] - a*m;
    }
}

// ---------- setup ----------
__global__ void k_zero() {
    int i = blockIdx.x*256 + threadIdx.x;
    if (i < NN) { g_deg[i] = 0; g_cursor[i] = 0; }
    if (i < 1024) { g_sum[i] = 0.f; g_sq[i] = 0.f; }
    if (i < NG*D) g_gsum[i] = 0.f;
    if (i < NG)   g_gcnt[i] = 0.f;
}

__global__ void k_hist(const int* __restrict__ dst) {
    int e = blockIdx.x*256 + threadIdx.x;
    if (e < NE) atomicAdd(&g_deg[dst[e]], 1);
}

__global__ void k_scan() {
    __shared__ int wsum[32];
    __shared__ int carry;
    int t = threadIdx.x, lane = t & 31, w = t >> 5;
    if (t == 0) carry = 0;
    __syncthreads();
    for (int base = 0; base < NN; base += 1024) {
        int i = base + t;
        int v = (i < NN) ? g_deg[i] : 0;
        int x = v;
        for (int o = 1; o < 32; o <<= 1) { int y = __shfl_up_sync(~0u, x, o); if (lane >= o) x += y; }
        if (lane == 31) wsum[w] = x;
        __syncthreads();
        if (w == 0) {
            int s = wsum[lane];
            for (int o = 1; o < 32; o <<= 1) { int y = __shfl_up_sync(~0u, s, o); if (lane >= o) s += y; }
            wsum[lane] = s;
        }
        __syncthreads();
        int excl = carry + x - v + ((w > 0) ? wsum[w-1] : 0);
        if (i < NN) g_rowstart[i] = excl;
        __syncthreads();
        if (t == 0) carry += wsum[31];
        __syncthreads();
    }
    if (threadIdx.x == 0) g_rowstart[NN] = carry;
}

__global__ void k_scatter(const int* __restrict__ dst) {
    int e = blockIdx.x*256 + threadIdx.x;
    if (e < NE) {
        int d = dst[e];
        g_eidx[g_rowstart[d] + atomicAdd(&g_cursor[d], 1)] = e;
    }
}

// ---------- input projection ----------
__global__ void k_lin_in(const float* __restrict__ x, const float* __restrict__ W,
                         const float* __restrict__ b) {
    __shared__ float Ws[IND*D];
    __shared__ float bs[D];
    for (int i = threadIdx.x; i < IND*D; i += 256) Ws[i] = W[i];
    if (threadIdx.x < D) bs[threadIdx.x] = b[threadIdx.x];
    __syncthreads();
    int t = blockIdx.x*256 + threadIdx.x;
    int node = t >> 2, c0 = (t & 3) * 16;
    if (node >= NN) return;
    float xs[IND];
#pragma unroll
    for (int k = 0; k < IND; k++) xs[k] = x[node*IND + k];
#pragma unroll
    for (int j = 0; j < 16; j++) {
        int c = c0 + j;
        float acc = bs[c];
#pragma unroll
        for (int k = 0; k < IND; k++) acc = fmaf(xs[k], Ws[k*D + c], acc);
        g_h[node*D + c] = acc;
    }
}

// ---------- 128x64x64 GEMM core ----------
__device__ __forceinline__ void gemm_8x8(const float* __restrict__ As,
                                         const float* __restrict__ Ws,
                                         int e0, int j0, float acc[8][8]) {
#pragma unroll 8
    for (int k = 0; k < 64; k++) {
        float4 a0 = *(const float4*)(As + k*128 + e0);
        float4 a1 = *(const float4*)(As + k*128 + e0 + 4);
        float4 w0 = *(const float4*)(Ws + k*64 + j0);
        float4 w1 = *(const float4*)(Ws + k*64 + j0 + 4);
        float av[8] = {a0.x,a0.y,a0.z,a0.w,a1.x,a1.y,a1.z,a1.w};
        float wv[8] = {w0.x,w0.y,w0.z,w0.w,w1.x,w1.y,w1.z,w1.w};
#pragma unroll
        for (int i = 0; i < 8; i++)
#pragma unroll
            for (int j = 0; j < 8; j++)
                acc[i][j] = fmaf(av[i], wv[j], acc[i][j]);
    }
}

__device__ __forceinline__ void load_h_to_As(float* As, const float* srcbuf, int n, int t, bool valid) {
    if (valid) {
#pragma unroll
        for (int kb = 0; kb < 16; kb++) {
            float4 v = *(const float4*)(srcbuf + n*64 + kb*4);
            int c = kb*4;
            As[(c+0)*128+t] = v.x; As[(c+1)*128+t] = v.y;
            As[(c+2)*128+t] = v.z; As[(c+3)*128+t] = v.w;
        }
    } else {
#pragma unroll
        for (int k = 0; k < 64; k++) As[k*128+t] = 0.f;
    }
}

// ---------- P = h@Wd + b1, Q = h@Ws ----------
#define SM_PQ ((8192 + 4096 + 64) * 4)
__global__ void __launch_bounds__(128) k_nodePQ(const float* __restrict__ W1,
                                                const float* __restrict__ b1) {
    extern __shared__ float sm[];
    float* As = sm; float* Ws = sm + 8192; float* b1s = Ws + 4096;
    int t = threadIdx.x, base = blockIdx.x*128, n = base + t;
    load_h_to_As(As, g_h, n, t, n < NN);
    if (t < 64) b1s[t] = b1[t];
    for (int i = t; i < 4096; i += 128) Ws[i] = W1[i];
    __syncthreads();
    int e0 = (t >> 3) * 8, j0 = (t & 7) * 8;
    float acc[8][8];
#pragma unroll
    for (int i = 0; i < 8; i++)
#pragma unroll
        for (int j = 0; j < 8; j++) acc[i][j] = 0.f;
    gemm_8x8(As, Ws, e0, j0, acc);
#pragma unroll
    for (int i = 0; i < 8; i++) {
        int nn = base + e0 + i;
        if (nn < NN) {
            float4 o0 = {acc[i][0]+b1s[j0], acc[i][1]+b1s[j0+1], acc[i][2]+b1s[j0+2], acc[i][3]+b1s[j0+3]};
            float4 o1 = {acc[i][4]+b1s[j0+4], acc[i][5]+b1s[j0+5], acc[i][6]+b1s[j0+6], acc[i][7]+b1s[j0+7]};
            *(float4*)(g_P + nn*64 + j0) = o0;
            *(float4*)(g_P + nn*64 + j0 + 4) = o1;
        }
    }
    __syncthreads();
    for (int i = t; i < 4096; i += 128) Ws[i] = W1[4096 + i];
    __syncthreads();
#pragma unroll
    for (int i = 0; i < 8; i++)
#pragma unroll
        for (int j = 0; j < 8; j++) acc[i][j] = 0.f;
    gemm_8x8(As, Ws, e0, j0, acc);
#pragma unroll
    for (int i = 0; i < 8; i++) {
        int nn = base + e0 + i;
        if (nn < NN) {
            float4 o0 = {acc[i][0], acc[i][1], acc[i][2], acc[i][3]};
            float4 o1 = {acc[i][4], acc[i][5], acc[i][6], acc[i][7]};
            *(float4*)(g_Q + nn*64 + j0) = o0;
            *(float4*)(g_Q + nn*64 + j0 + 4) = o1;
        }
    }
}

// ---------- pass A: y1 stats -> slot ----------
__global__ void k_edgeA(const int* __restrict__ src, const int* __restrict__ dst,
                        const float* __restrict__ ea, const float* __restrict__ W1, int slot) {
    __shared__ float Weas[256];
    __shared__ float ssum[64], ssq[64];
    int t = threadIdx.x;
    for (int i = t; i < 256; i += 256) Weas[i] = W1[8192 + i];
    if (t < 64) { ssum[t] = 0.f; ssq[t] = 0.f; }
    __syncthreads();
    int wg = (blockIdx.x*256 + t) >> 5, lane = t & 31;
    int nw = (gridDim.x*256) >> 5;
    float s0 = 0.f, s1 = 0.f, q0 = 0.f, q1 = 0.f;
    for (int e = wg; e < NE; e += nw) {
        int s = src[e], d = dst[e];
        float4 ev = *(const float4*)(ea + e*4);
        int c = lane;
        float y = g_P[d*64+c] + g_Q[s*64+c]
                + ev.x*Weas[c] + ev.y*Weas[64+c] + ev.z*Weas[128+c] + ev.w*Weas[192+c];
        s0 += y; q0 += y*y;
        c = lane + 32;
        float z = g_P[d*64+c] + g_Q[s*64+c]
                + ev.x*Weas[c] + ev.y*Weas[64+c] + ev.z*Weas[128+c] + ev.w*Weas[192+c];
        s1 += z; q1 += z*z;
    }
    atomicAdd(&ssum[lane], s0); atomicAdd(&ssum[lane+32], s1);
    atomicAdd(&ssq[lane],  q0); atomicAdd(&ssq[lane+32],  q1);
    __syncthreads();
    if (t < 64) { atomicAdd(&g_sum[slot*64+t], ssum[t]); atomicAdd(&g_sq[slot*64+t], ssq[t]); }
}

// ---------- pass B: bn1+relu, y2 = m1@W2+b2 (bf16 store), stats2 ----------
#define SM_EB ((8192 + 4096 + 256 + 64 + 64 + 64 + 256 + 256) * 4)
__global__ void __launch_bounds__(128) k_edgeB(const int* __restrict__ src, const int* __restrict__ dst,
                                               const float* __restrict__ ea, const float* __restrict__ W1,
                                               const float* __restrict__ W2, const float* __restrict__ b2,
                                               const float* __restrict__ g1, const float* __restrict__ be1,
                                               int slot_in, int slot_out) {
    extern __shared__ float sm[];
    float* As = sm; float* Ws = As + 8192; float* Weas = Ws + 4096;
    float* al = Weas + 256; float* be = al + 64; float* b2s = be + 64;
    float* ssum = b2s + 64; float* ssq = ssum + 256;
    int t = threadIdx.x, base = blockIdx.x*128, e = base + t;
    for (int i = t; i < 4096; i += 128) Ws[i] = W2[i];
    for (int i = t; i < 256; i += 128) { Weas[i] = W1[8192 + i]; ssum[i] = 0.f; ssq[i] = 0.f; }
    bnprep(al, be, slot_in, 1.f/NE, g1, be1, t);
    if (t < 64) b2s[t] = b2[t];
    __syncthreads();
    int d0 = dst[e], s0 = src[e];
    float4 ev = *(const float4*)(ea + e*4);
    const float4* Pp = (const float4*)(g_P + d0*64);
    const float4* Qp = (const float4*)(g_Q + s0*64);
#pragma unroll
    for (int kb = 0; kb < 16; kb++) {
        float4 p = Pp[kb], q = Qp[kb];
        int c = kb*4;
#pragma unroll
        for (int u = 0; u < 4; u++) {
            float pv = (u==0)?p.x:(u==1)?p.y:(u==2)?p.z:p.w;
            float qv = (u==0)?q.x:(u==1)?q.y:(u==2)?q.z:q.w;
            int cc = c + u;
            float y = pv + qv + ev.x*Weas[cc] + ev.y*Weas[64+cc] + ev.z*Weas[128+cc] + ev.w*Weas[192+cc];
            As[cc*128+t] = fmaxf(fmaf(al[cc], y, be[cc]), 0.f);
        }
    }
    __syncthreads();
    int e0 = (t >> 3) * 8, j0 = (t & 7) * 8;
    float acc[8][8];
#pragma unroll
    for (int i = 0; i < 8; i++)
#pragma unroll
        for (int j = 0; j < 8; j++) acc[i][j] = 0.f;
    gemm_8x8(As, Ws, e0, j0, acc);
    float cs[8], cq[8];
#pragma unroll
    for (int j = 0; j < 8; j++) { cs[j] = 0.f; cq[j] = 0.f; }
#pragma unroll
    for (int i = 0; i < 8; i++) {
        float v[8];
#pragma unroll
        for (int j = 0; j < 8; j++) { v[j] = acc[i][j] + b2s[j0+j]; cs[j] += v[j]; cq[j] += v[j]*v[j]; }
        __nv_bfloat162 p0 = __floats2bfloat162_rn(v[0], v[1]);
        __nv_bfloat162 p1 = __floats2bfloat162_rn(v[2], v[3]);
        __nv_bfloat162 p2 = __floats2bfloat162_rn(v[4], v[5]);
        __nv_bfloat162 p3 = __floats2bfloat162_rn(v[6], v[7]);
        uint4 o;
        o.x = *(unsigned*)&p0; o.y = *(unsigned*)&p1; o.z = *(unsigned*)&p2; o.w = *(unsigned*)&p3;
        *(uint4*)(g_y2 + (base+e0+i)*64 + j0) = o;
    }
    int w = t >> 5;
#pragma unroll
    for (int j = 0; j < 8; j++) {
        atomicAdd(&ssum[w*64 + j0 + j], cs[j]);
        atomicAdd(&ssq [w*64 + j0 + j], cq[j]);
    }
    __syncthreads();
    if (t < 64) {
        atomicAdd(&g_sum[slot_out*64+t], ssum[t]+ssum[64+t]+ssum[128+t]+ssum[192+t]);
        atomicAdd(&g_sq [slot_out*64+t], ssq [t]+ssq [64+t]+ssq [128+t]+ssq [192+t]);
    }
}

// ---------- CSR aggregation (bn2+relu fused, bf16 reads) ----------
__global__ void __launch_bounds__(256) k_aggr(const float* __restrict__ g2, const float* __restrict__ be2, int slot) {
    __shared__ float al[64], be[64];
    bnprep(al, be, slot, 1.f/NE, g2, be2, threadIdx.x);
    __syncthreads();
    int w = (blockIdx.x*256 + threadIdx.x) >> 5;
    if (w >= NN) return;
    int lane = threadIdx.x & 31;
    float alA = al[2*lane], beA = be[2*lane];
    float alB = al[2*lane+1], beB = be[2*lane+1];
    const __nv_bfloat162* y = (const __nv_bfloat162*)g_y2;
    float a0 = 0.f, a1 = 0.f;
    int s = g_rowstart[w], e = g_rowstart[w+1];
    for (int p = s; p < e; p++) {
        int eid = g_eidx[p];
        float2 v = __bfloat1622float2(y[eid*32 + lane]);
        a0 += fmaxf(fmaf(alA, v.x, beA), 0.f);
        a1 += fmaxf(fmaf(alB, v.y, beB), 0.f);
    }
    float2 o = {a0, a1};
    *(float2*)(g_aggr + w*64 + 2*lane) = o;
}

// ---------- node update 1 ----------
#define SM_U1 ((8192 + 4096 + 64 + 256 + 256) * 4)
__global__ void __launch_bounds__(128) k_nodeU1(const float* __restrict__ W,
                                                const float* __restrict__ b3, int slot_out) {
    extern __shared__ float sm[];
    float* As = sm; float* Ws = As + 8192; float* b3s = Ws + 4096;
    float* ssum = b3s + 64; float* ssq = ssum + 256;
    int t = threadIdx.x, base = blockIdx.x*128, n = base + t;
    load_h_to_As(As, g_h, n, t, n < NN);
    for (int i = t; i < 4096; i += 128) Ws[i] = W[i];
    if (t < 64) b3s[t] = b3[t];
    for (int i = t; i < 256; i += 128) { ssum[i] = 0.f; ssq[i] = 0.f; }
    __syncthreads();
    int e0 = (t >> 3) * 8, j0 = (t & 7) * 8;
    float acc[8][8];
#pragma unroll
    for (int i = 0; i < 8; i++)
#pragma unroll
        for (int j = 0; j < 8; j++) acc[i][j] = 0.f;
    gemm_8x8(As, Ws, e0, j0, acc);
    __syncthreads();
    load_h_to_As(As, g_aggr, n, t, n < NN);
    for (int i = t; i < 4096; i += 128) Ws[i] = W[4096 + i];
    __syncthreads();
    gemm_8x8(As, Ws, e0, j0, acc);
    float cs[8], cq[8];
#pragma unroll
    for (int j = 0; j < 8; j++) { cs[j] = 0.f; cq[j] = 0.f; }
#pragma unroll
    for (int i = 0; i < 8; i++) {
        int n2 = base + e0 + i;
        if (n2 < NN) {
            float v[8];
#pragma unroll
            for (int j = 0; j < 8; j++) { v[j] = acc[i][j] + b3s[j0+j]; cs[j] += v[j]; cq[j] += v[j]*v[j]; }
            float4 o0 = {v[0],v[1],v[2],v[3]};
            float4 o1 = {v[4],v[5],v[6],v[7]};
            *(float4*)(g_y3 + n2*64 + j0) = o0;
            *(float4*)(g_y3 + n2*64 + j0 + 4) = o1;
        }
    }
    int w = t >> 5;
#pragma unroll
    for (int j = 0; j < 8; j++) {
        atomicAdd(&ssum[w*64 + j0 + j], cs[j]);
        atomicAdd(&ssq [w*64 + j0 + j], cq[j]);
    }
    __syncthreads();
    if (t < 64) {
        atomicAdd(&g_sum[slot_out*64+t], ssum[t]+ssum[64+t]+ssum[128+t]+ssum[192+t]);
        atomicAdd(&g_sq [slot_out*64+t], ssq [t]+ssq [64+t]+ssq [128+t]+ssq [192+t]);
    }
}

// ---------- node update 2 ----------
#define SM_U2 ((8192 + 4096 + 64 + 64 + 64 + 256 + 256) * 4)
__global__ void __launch_bounds__(128) k_nodeU2(const float* __restrict__ W,
                                                const float* __restrict__ b4,
                                                const float* __restrict__ g3, const float* __restrict__ be3,
                                                int slot_in, int slot_out) {
    extern __shared__ float sm[];
    float* As = sm; float* Ws = As + 8192; float* al = Ws + 4096;
    float* be = al + 64; float* b4s = be + 64;
    float* ssum = b4s + 64; float* ssq = ssum + 256;
    int t = threadIdx.x, base = blockIdx.x*128, n = base + t;
    for (int i = t; i < 4096; i += 128) Ws[i] = W[i];
    bnprep(al, be, slot_in, 1.f/NN, g3, be3, t);
    if (t < 64) b4s[t] = b4[t];
    for (int i = t; i < 256; i += 128) { ssum[i] = 0.f; ssq[i] = 0.f; }
    __syncthreads();
    if (n < NN) {
#pragma unroll
        for (int kb = 0; kb < 16; kb++) {
            float4 v = *(const float4*)(g_y3 + n*64 + kb*4);
            int c = kb*4;
            As[(c+0)*128+t] = fmaxf(fmaf(al[c+0], v.x, be[c+0]), 0.f);
            As[(c+1)*128+t] = fmaxf(fmaf(al[c+1], v.y, be[c+1]), 0.f);
            As[(c+2)*128+t] = fmaxf(fmaf(al[c+2], v.z, be[c+2]), 0.f);
            As[(c+3)*128+t] = fmaxf(fmaf(al[c+3], v.w, be[c+3]), 0.f);
        }
    } else {
#pragma unroll
        for (int k = 0; k < 64; k++) As[k*128+t] = 0.f;
    }
    __syncthreads();
    int e0 = (t >> 3) * 8, j0 = (t & 7) * 8;
    float acc[8][8];
#pragma unroll
    for (int i = 0; i < 8; i++)
#pragma unroll
        for (int j = 0; j < 8; j++) acc[i][j] = 0.f;
    gemm_8x8(As, Ws, e0, j0, acc);
    float cs[8], cq[8];
#pragma unroll
    for (int j = 0; j < 8; j++) { cs[j] = 0.f; cq[j] = 0.f; }
#pragma unroll
    for (int i = 0; i < 8; i++) {
        int n2 = base + e0 + i;
        if (n2 < NN) {
            float v[8];
#pragma unroll
            for (int j = 0; j < 8; j++) { v[j] = acc[i][j] + b4s[j0+j]; cs[j] += v[j]; cq[j] += v[j]*v[j]; }
            float4 o0 = {v[0],v[1],v[2],v[3]};
            float4 o1 = {v[4],v[5],v[6],v[7]};
            *(float4*)(g_y4 + n2*64 + j0) = o0;
            *(float4*)(g_y4 + n2*64 + j0 + 4) = o1;
        }
    }
    int w = t >> 5;
#pragma unroll
    for (int j = 0; j < 8; j++) {
        atomicAdd(&ssum[w*64 + j0 + j], cs[j]);
        atomicAdd(&ssq [w*64 + j0 + j], cq[j]);
    }
    __syncthreads();
    if (t < 64) {
        atomicAdd(&g_sum[slot_out*64+t], ssum[t]+ssum[64+t]+ssum[128+t]+ssum[192+t]);
        atomicAdd(&g_sq [slot_out*64+t], ssq [t]+ssq [64+t]+ssq [128+t]+ssq [192+t]);
    }
}

// ---------- residual (bn4+relu fused) ----------
__global__ void __launch_bounds__(256) k_resid(const float* __restrict__ g4, const float* __restrict__ be4, int slot) {
    __shared__ float al[64], be[64];
    bnprep(al, be, slot, 1.f/NN, g4, be4, threadIdx.x);
    __syncthreads();
    int i = blockIdx.x*256 + threadIdx.x;
    if (i < NN*D) {
        int c = i & 63;
        g_h[i] += fmaxf(fmaf(al[c], g_y4[i], be[c]), 0.f);
    }
}

// ---------- pooling (warp-private running sums over sorted batch) ----------
__global__ void k_pool(const int* __restrict__ batch) {
    int w = blockIdx.x*8 + (threadIdx.x >> 5);
    int lane = threadIdx.x & 31;
    int n0 = w*64, n1 = min(n0 + 64, NN);
    if (n0 >= NN) return;
    float ax = 0.f, ay = 0.f, cnt = 0.f;
    int curg = batch[n0];
    for (int n = n0; n < n1; n++) {
        int g = batch[n];
        if (g != curg) {
            atomicAdd(&g_gsum[curg*64 + 2*lane], ax);
            atomicAdd(&g_gsum[curg*64 + 2*lane + 1], ay);
            if (lane == 0) atomicAdd(&g_gcnt[curg], cnt);
            ax = 0.f; ay = 0.f; cnt = 0.f; curg = g;
        }
        float2 v = *(const float2*)(g_h + n*64 + 2*lane);
        ax += v.x; ay += v.y; cnt += 1.f;
    }
    atomicAdd(&g_gsum[curg*64 + 2*lane], ax);
    atomicAdd(&g_gsum[curg*64 + 2*lane + 1], ay);
    if (lane == 0) atomicAdd(&g_gcnt[curg], cnt);
}

__global__ void k_pred(const float* __restrict__ pW, const float* __restrict__ pb,
                       float* __restrict__ out) {
    int g = threadIdx.x;
    if (g < NG) {
        float cnt = fmaxf(g_gcnt[g], 1.f);
        float acc = pb[0];
        for (int c = 0; c < D; c++) acc += g_gsum[g*64 + c] / cnt * pW[c];
        out[g] = acc;
    }
}

extern "C" void kernel_launch(void* const* d_in, const int* in_sizes, int n_in,
                              void* d_out, int out_size) {
    const float* x    = (const float*)d_in[0];
    const float* ea   = (const float*)d_in[1];
    const int*   ei   = (const int*)d_in[2];
    const int*   batch= (const int*)d_in[3];
    const float* linW = (const float*)d_in[4];
    const float* linb = (const float*)d_in[5];
    const float* mW1  = (const float*)d_in[6];
    const float* mb1  = (const float*)d_in[7];
    const float* mg1  = (const float*)d_in[8];
    const float* mbe1 = (const float*)d_in[9];
    const float* mW2  = (const float*)d_in[10];
    const float* mb2  = (const float*)d_in[11];
    const float* mg2  = (const float*)d_in[12];
    const float* mbe2 = (const float*)d_in[13];
    const float* uW1  = (const float*)d_in[14];
    const float* ub1  = (const float*)d_in[15];
    const float* ug1  = (const float*)d_in[16];
    const float* ube1 = (const float*)d_in[17];
    const float* uW2  = (const float*)d_in[18];
    const float* ub2  = (const float*)d_in[19];
    const float* ug2  = (const float*)d_in[20];
    const float* ube2 = (const float*)d_in[21];
    const float* pW   = (const float*)d_in[22];
    const float* pb   = (const float*)d_in[23];
    float* out = (float*)d_out;
    const int* src = ei;
    const int* dst = ei + NE;

    cudaFuncSetAttribute(k_nodePQ, cudaFuncAttributeMaxDynamicSharedMemorySize, SM_PQ);
    cudaFuncSetAttribute(k_edgeB,  cudaFuncAttributeMaxDynamicSharedMemorySize, SM_EB);
    cudaFuncSetAttribute(k_nodeU1, cudaFuncAttributeMaxDynamicSharedMemorySize, SM_U1);
    cudaFuncSetAttribute(k_nodeU2, cudaFuncAttributeMaxDynamicSharedMemorySize, SM_U2);

    k_zero<<<(NN+255)/256, 256>>>();
    k_hist<<<(NE+255)/256, 256>>>(dst);
    k_scan<<<1, 1024>>>();
    k_scatter<<<(NE+255)/256, 256>>>(dst);
    k_lin_in<<<(NN*4+255)/256, 256>>>(x, linW, linb);

    int nblk = (NN + 127) / 128;
    for (int l = 0; l < 4; l++) {
        const float* W1 = mW1 + l*132*64;
        int s0 = l*4;
        k_nodePQ<<<nblk, 128, SM_PQ>>>(W1, mb1 + l*64);
        k_edgeA<<<512, 256>>>(src, dst, ea, W1, s0);
        k_edgeB<<<NE/128, 128, SM_EB>>>(src, dst, ea, W1, mW2 + l*4096, mb2 + l*64,
                                        mg1 + l*64, mbe1 + l*64, s0, s0+1);
        k_aggr<<<(NN*32+255)/256, 256>>>(mg2 + l*64, mbe2 + l*64, s0+1);
        k_nodeU1<<<nblk, 128, SM_U1>>>(uW1 + l*128*64, ub1 + l*64, s0+2);
        k_nodeU2<<<nblk, 128, SM_U2>>>(uW2 + l*4096, ub2 + l*64,
                                       ug1 + l*64, ube1 + l*64, s0+2, s0+3);
        k_resid<<<(NN*D+255)/256, 256>>>(ug2 + l*64, ube2 + l*64, s0+3);
    }
    k_pool<<<(6250+7)/8 + 1, 256>>>(batch);
    k_pred<<<1, 32>>>(pW, pb, out);
}

// round 4
// speedup vs baseline: 1.1932x; 1.0834x over previous
#include <cuda_runtime.h>
#include <cuda_bf16.h>

#define NN 50000
#define NE 400000
#define NG 32
#define D  64
#define IND 11
#define EPSB 1e-5f

typedef unsigned long long u64;

#define F2FMA(acc, a, b) asm("fma.rn.f32x2 %0, %1, %2, %0;" : "+l"(acc) : "l"(a), "l"(b))
#define F2ADD(d, a, b)   asm("add.rn.f32x2 %0, %1, %2;" : "=l"(d) : "l"(a), "l"(b))
#define F2BCAST(d, x)    { unsigned _u = __float_as_uint(x); asm("mov.b64 %0, {%1, %1};" : "=l"(d) : "r"(_u)); }
#define F2UNPACK(lo, hi, p) { unsigned _a, _b; asm("mov.b64 {%0, %1}, %2;" : "=r"(_a), "=r"(_b) : "l"(p)); lo = __uint_as_float(_a); hi = __uint_as_float(_b); }

__device__ float g_h[NN*D];
__device__ float g_P[NN*D];
__device__ float g_Q[NN*D];
__device__ __nv_bfloat16 g_y2[NE*D];
__device__ float g_aggr[NN*D];
__device__ float g_y3[NN*D];
__device__ float g_y4[NN*D];
__device__ float g_sum[16*64];
__device__ float g_sq[16*64];
__device__ float g_gsum[NG*D];
__device__ float g_gcnt[NG];
__device__ int g_deg[NN];
__device__ int g_rowstart[NN+1];
__device__ int g_cursor[NN];
__device__ int g_eidx[NE];

__device__ __forceinline__ void bnprep(float* al, float* bes, int slot, float invn,
                                       const float* __restrict__ g,
                                       const float* __restrict__ bb, int t) {
    if (t < 64) {
        float m = g_sum[slot*64+t] * invn;
        float v = fmaxf(g_sq[slot*64+t] * invn - m*m, 0.f);
        float a = g[t] * rsqrtf(v + EPSB);
        al[t] = a; bes[t] = bb[t] - a*m;
    }
}

// ---------- setup ----------
__global__ void k_zero() {
    int i = blockIdx.x*256 + threadIdx.x;
    if (i < NN) { g_deg[i] = 0; g_cursor[i] = 0; }
    if (i < 1024) { g_sum[i] = 0.f; g_sq[i] = 0.f; }
    if (i < NG*D) g_gsum[i] = 0.f;
    if (i < NG)   g_gcnt[i] = 0.f;
}

__global__ void k_hist(const int* __restrict__ dst) {
    int e = blockIdx.x*256 + threadIdx.x;
    if (e < NE) atomicAdd(&g_deg[dst[e]], 1);
}

__global__ void k_scan() {
    __shared__ int wsum[32];
    __shared__ int carry;
    int t = threadIdx.x, lane = t & 31, w = t >> 5;
    if (t == 0) carry = 0;
    __syncthreads();
    for (int base = 0; base < NN; base += 1024) {
        int i = base + t;
        int v = (i < NN) ? g_deg[i] : 0;
        int x = v;
        for (int o = 1; o < 32; o <<= 1) { int y = __shfl_up_sync(~0u, x, o); if (lane >= o) x += y; }
        if (lane == 31) wsum[w] = x;
        __syncthreads();
        if (w == 0) {
            int s = wsum[lane];
            for (int o = 1; o < 32; o <<= 1) { int y = __shfl_up_sync(~0u, s, o); if (lane >= o) s += y; }
            wsum[lane] = s;
        }
        __syncthreads();
        int excl = carry + x - v + ((w > 0) ? wsum[w-1] : 0);
        if (i < NN) g_rowstart[i] = excl;
        __syncthreads();
        if (t == 0) carry += wsum[31];
        __syncthreads();
    }
    if (threadIdx.x == 0) g_rowstart[NN] = carry;
}

__global__ void k_scatter(const int* __restrict__ dst) {
    int e = blockIdx.x*256 + threadIdx.x;
    if (e < NE) {
        int d = dst[e];
        g_eidx[g_rowstart[d] + atomicAdd(&g_cursor[d], 1)] = e;
    }
}

// ---------- input projection ----------
__global__ void k_lin_in(const float* __restrict__ x, const float* __restrict__ W,
                         const float* __restrict__ b) {
    __shared__ float Ws[IND*D];
    __shared__ float bs[D];
    for (int i = threadIdx.x; i < IND*D; i += 256) Ws[i] = W[i];
    if (threadIdx.x < D) bs[threadIdx.x] = b[threadIdx.x];
    __syncthreads();
    int t = blockIdx.x*256 + threadIdx.x;
    int node = t >> 2, c0 = (t & 3) * 16;
    if (node >= NN) return;
    float xs[IND];
#pragma unroll
    for (int k = 0; k < IND; k++) xs[k] = x[node*IND + k];
#pragma unroll
    for (int j = 0; j < 16; j++) {
        int c = c0 + j;
        float acc = bs[c];
#pragma unroll
        for (int k = 0; k < IND; k++) acc = fmaf(xs[k], Ws[k*D + c], acc);
        g_h[node*D + c] = acc;
    }
}

// ---------- packed-f32x2 128x64x64 GEMM core ----------
// acc: 32 u64 (8 rows x 4 col-pairs)
__device__ __forceinline__ void gemm_8x8p(const float* __restrict__ As,
                                          const float* __restrict__ Ws,
                                          int e0, int j0, u64* acc) {
#pragma unroll 8
    for (int k = 0; k < 64; k++) {
        float4 a0 = *(const float4*)(As + k*128 + e0);
        float4 a1 = *(const float4*)(As + k*128 + e0 + 4);
        ulonglong2 w01 = *(const ulonglong2*)(Ws + k*64 + j0);
        ulonglong2 w23 = *(const ulonglong2*)(Ws + k*64 + j0 + 4);
        u64 wp0 = w01.x, wp1 = w01.y, wp2 = w23.x, wp3 = w23.y;
        float av[8] = {a0.x,a0.y,a0.z,a0.w,a1.x,a1.y,a1.z,a1.w};
#pragma unroll
        for (int i = 0; i < 8; i++) {
            u64 ap; F2BCAST(ap, av[i]);
            F2FMA(acc[i*4+0], ap, wp0);
            F2FMA(acc[i*4+1], ap, wp1);
            F2FMA(acc[i*4+2], ap, wp2);
            F2FMA(acc[i*4+3], ap, wp3);
        }
    }
}

__device__ __forceinline__ void unpack_row(const u64* accrow, float* v) {
#pragma unroll
    for (int jp = 0; jp < 4; jp++) F2UNPACK(v[2*jp], v[2*jp+1], accrow[jp]);
}

__device__ __forceinline__ void load_h_to_As(float* As, const float* srcbuf, int n, int t, bool valid) {
    if (valid) {
#pragma unroll
        for (int kb = 0; kb < 16; kb++) {
            float4 v = *(const float4*)(srcbuf + n*64 + kb*4);
            int c = kb*4;
            As[(c+0)*128+t] = v.x; As[(c+1)*128+t] = v.y;
            As[(c+2)*128+t] = v.z; As[(c+3)*128+t] = v.w;
        }
    } else {
#pragma unroll
        for (int k = 0; k < 64; k++) As[k*128+t] = 0.f;
    }
}

// ---------- P = h@Wd + b1, Q = h@Ws ----------
#define SM_PQ ((8192 + 4096 + 64) * 4)
__global__ void __launch_bounds__(128) k_nodePQ(const float* __restrict__ W1,
                                                const float* __restrict__ b1) {
    extern __shared__ float sm[];
    float* As = sm; float* Ws = sm + 8192; float* b1s = Ws + 4096;
    int t = threadIdx.x, base = blockIdx.x*128, n = base + t;
    load_h_to_As(As, g_h, n, t, n < NN);
    if (t < 64) b1s[t] = b1[t];
    for (int i = t; i < 4096; i += 128) Ws[i] = W1[i];
    __syncthreads();
    int e0 = (t >> 3) * 8, j0 = (t & 7) * 8;
    u64 acc[32];
#pragma unroll
    for (int i = 0; i < 32; i++) acc[i] = 0ull;
    gemm_8x8p(As, Ws, e0, j0, acc);
#pragma unroll
    for (int i = 0; i < 8; i++) {
        int nn = base + e0 + i;
        if (nn < NN) {
            float v[8]; unpack_row(acc + i*4, v);
            float4 o0 = {v[0]+b1s[j0], v[1]+b1s[j0+1], v[2]+b1s[j0+2], v[3]+b1s[j0+3]};
            float4 o1 = {v[4]+b1s[j0+4], v[5]+b1s[j0+5], v[6]+b1s[j0+6], v[7]+b1s[j0+7]};
            *(float4*)(g_P + nn*64 + j0) = o0;
            *(float4*)(g_P + nn*64 + j0 + 4) = o1;
        }
    }
    __syncthreads();
    for (int i = t; i < 4096; i += 128) Ws[i] = W1[4096 + i];
    __syncthreads();
#pragma unroll
    for (int i = 0; i < 32; i++) acc[i] = 0ull;
    gemm_8x8p(As, Ws, e0, j0, acc);
#pragma unroll
    for (int i = 0; i < 8; i++) {
        int nn = base + e0 + i;
        if (nn < NN) {
            float v[8]; unpack_row(acc + i*4, v);
            float4 o0 = {v[0], v[1], v[2], v[3]};
            float4 o1 = {v[4], v[5], v[6], v[7]};
            *(float4*)(g_Q + nn*64 + j0) = o0;
            *(float4*)(g_Q + nn*64 + j0 + 4) = o1;
        }
    }
}

// ---------- pass A: y1 stats (packed pairs per lane) ----------
__global__ void k_edgeA(const int* __restrict__ src, const int* __restrict__ dst,
                        const float* __restrict__ ea, const float* __restrict__ W1, int slot) {
    __shared__ float Weas[256];
    __shared__ float ssum[64], ssq[64];
    int t = threadIdx.x;
    for (int i = t; i < 256; i += 256) Weas[i] = W1[8192 + i];
    if (t < 64) { ssum[t] = 0.f; ssq[t] = 0.f; }
    __syncthreads();
    int wg = (blockIdx.x*256 + t) >> 5, lane = t & 31;
    int nw = (gridDim.x*256) >> 5;
    int c2 = 2*lane;
    u64 w0 = *(const u64*)(Weas + c2);
    u64 w1 = *(const u64*)(Weas + 64 + c2);
    u64 w2 = *(const u64*)(Weas + 128 + c2);
    u64 w3 = *(const u64*)(Weas + 192 + c2);
    u64 sp = 0ull, qp = 0ull;
    for (int e = wg; e < NE; e += nw) {
        int s = src[e], d = dst[e];
        float4 ev = *(const float4*)(ea + e*4);
        u64 e0, e1, e2, e3;
        F2BCAST(e0, ev.x); F2BCAST(e1, ev.y); F2BCAST(e2, ev.z); F2BCAST(e3, ev.w);
        u64 Pv = *(const u64*)(g_P + d*64 + c2);
        u64 Qv = *(const u64*)(g_Q + s*64 + c2);
        u64 y; F2ADD(y, Pv, Qv);
        F2FMA(y, e0, w0); F2FMA(y, e1, w1); F2FMA(y, e2, w2); F2FMA(y, e3, w3);
        F2ADD(sp, sp, y);
        F2FMA(qp, y, y);
    }
    float sl, sh, ql, qh;
    F2UNPACK(sl, sh, sp); F2UNPACK(ql, qh, qp);
    atomicAdd(&ssum[c2], sl); atomicAdd(&ssum[c2+1], sh);
    atomicAdd(&ssq[c2],  ql); atomicAdd(&ssq[c2+1],  qh);
    __syncthreads();
    if (t < 64) { atomicAdd(&g_sum[slot*64+t], ssum[t]); atomicAdd(&g_sq[slot*64+t], ssq[t]); }
}

// ---------- pass B: bn1+relu, y2 = m1@W2+b2 (bf16 store), stats2 ----------
#define SM_EB ((8192 + 4096 + 256 + 64 + 64 + 64 + 256 + 256) * 4)
__global__ void __launch_bounds__(128) k_edgeB(const int* __restrict__ src, const int* __restrict__ dst,
                                               const float* __restrict__ ea, const float* __restrict__ W1,
                                               const float* __restrict__ W2, const float* __restrict__ b2,
                                               const float* __restrict__ g1, const float* __restrict__ be1,
                                               int slot_in, int slot_out) {
    extern __shared__ float sm[];
    float* As = sm; float* Ws = As + 8192; float* Weas = Ws + 4096;
    float* al = Weas + 256; float* be = al + 64; float* b2s = be + 64;
    float* ssum = b2s + 64; float* ssq = ssum + 256;
    int t = threadIdx.x, base = blockIdx.x*128, e = base + t;
    for (int i = t; i < 4096; i += 128) Ws[i] = W2[i];
    for (int i = t; i < 256; i += 128) { Weas[i] = W1[8192 + i]; ssum[i] = 0.f; ssq[i] = 0.f; }
    bnprep(al, be, slot_in, 1.f/NE, g1, be1, t);
    if (t < 64) b2s[t] = b2[t];
    __syncthreads();
    int d0 = dst[e], s0 = src[e];
    float4 ev = *(const float4*)(ea + e*4);
    u64 eb0, eb1, eb2, eb3;
    F2BCAST(eb0, ev.x); F2BCAST(eb1, ev.y); F2BCAST(eb2, ev.z); F2BCAST(eb3, ev.w);
#pragma unroll
    for (int kb = 0; kb < 16; kb++) {
        int c = kb*4;
        ulonglong2 Pv = *(const ulonglong2*)(g_P + d0*64 + c);
        ulonglong2 Qv = *(const ulonglong2*)(g_Q + s0*64 + c);
#pragma unroll
        for (int h = 0; h < 2; h++) {
            int cc = c + 2*h;
            u64 y; F2ADD(y, h ? Pv.y : Pv.x, h ? Qv.y : Qv.x);
            F2FMA(y, eb0, *(const u64*)(Weas + cc));
            F2FMA(y, eb1, *(const u64*)(Weas + 64 + cc));
            F2FMA(y, eb2, *(const u64*)(Weas + 128 + cc));
            F2FMA(y, eb3, *(const u64*)(Weas + 192 + cc));
            // bn: z = al*y + be (packed), then relu scalar
            u64 alp = *(const u64*)(al + cc);
            u64 bep = *(const u64*)(be + cc);
            u64 z = bep;
            F2FMA(z, alp, y);
            float zl, zh; F2UNPACK(zl, zh, z);
            As[cc*128 + t]     = fmaxf(zl, 0.f);
            As[(cc+1)*128 + t] = fmaxf(zh, 0.f);
        }
    }
    __syncthreads();
    int e0 = (t >> 3) * 8, j0 = (t & 7) * 8;
    u64 acc[32];
#pragma unroll
    for (int i = 0; i < 32; i++) acc[i] = 0ull;
    gemm_8x8p(As, Ws, e0, j0, acc);
    float cs[8], cq[8];
#pragma unroll
    for (int j = 0; j < 8; j++) { cs[j] = 0.f; cq[j] = 0.f; }
#pragma unroll
    for (int i = 0; i < 8; i++) {
        float v[8]; unpack_row(acc + i*4, v);
#pragma unroll
        for (int j = 0; j < 8; j++) { v[j] += b2s[j0+j]; cs[j] += v[j]; cq[j] += v[j]*v[j]; }
        __nv_bfloat162 p0 = __floats2bfloat162_rn(v[0], v[1]);
        __nv_bfloat162 p1 = __floats2bfloat162_rn(v[2], v[3]);
        __nv_bfloat162 p2 = __floats2bfloat162_rn(v[4], v[5]);
        __nv_bfloat162 p3 = __floats2bfloat162_rn(v[6], v[7]);
        uint4 o;
        o.x = *(unsigned*)&p0; o.y = *(unsigned*)&p1; o.z = *(unsigned*)&p2; o.w = *(unsigned*)&p3;
        *(uint4*)(g_y2 + (base+e0+i)*64 + j0) = o;
    }
    int w = t >> 5;
#pragma unroll
    for (int j = 0; j < 8; j++) {
        atomicAdd(&ssum[w*64 + j0 + j], cs[j]);
        atomicAdd(&ssq [w*64 + j0 + j], cq[j]);
    }
    __syncthreads();
    if (t < 64) {
        atomicAdd(&g_sum[slot_out*64+t], ssum[t]+ssum[64+t]+ssum[128+t]+ssum[192+t]);
        atomicAdd(&g_sq [slot_out*64+t], ssq [t]+ssq [64+t]+ssq [128+t]+ssq [192+t]);
    }
}

// ---------- CSR aggregation (bn2+relu fused, bf16 reads) ----------
__global__ void __launch_bounds__(256) k_aggr(const float* __restrict__ g2, const float* __restrict__ be2, int slot) {
    __shared__ float al[64], be[64];
    bnprep(al, be, slot, 1.f/NE, g2, be2, threadIdx.x);
    __syncthreads();
    int w = (blockIdx.x*256 + threadIdx.x) >> 5;
    if (w >= NN) return;
    int lane = threadIdx.x & 31;
    float alA = al[2*lane], beA = be[2*lane];
    float alB = al[2*lane+1], beB = be[2*lane+1];
    const __nv_bfloat162* y = (const __nv_bfloat162*)g_y2;
    float a0 = 0.f, a1 = 0.f;
    int s = g_rowstart[w], e = g_rowstart[w+1];
    for (int p = s; p < e; p++) {
        int eid = g_eidx[p];
        float2 v = __bfloat1622float2(y[eid*32 + lane]);
        a0 += fmaxf(fmaf(alA, v.x, beA), 0.f);
        a1 += fmaxf(fmaf(alB, v.y, beB), 0.f);
    }
    float2 o = {a0, a1};
    *(float2*)(g_aggr + w*64 + 2*lane) = o;
}

// ---------- node update 1 ----------
#define SM_U1 ((8192 + 4096 + 64 + 256 + 256) * 4)
__global__ void __launch_bounds__(128) k_nodeU1(const float* __restrict__ W,
                                                const float* __restrict__ b3, int slot_out) {
    extern __shared__ float sm[];
    float* As = sm; float* Ws = As + 8192; float* b3s = Ws + 4096;
    float* ssum = b3s + 64; float* ssq = ssum + 256;
    int t = threadIdx.x, base = blockIdx.x*128, n = base + t;
    load_h_to_As(As, g_h, n, t, n < NN);
    for (int i = t; i < 4096; i += 128) Ws[i] = W[i];
    if (t < 64) b3s[t] = b3[t];
    for (int i = t; i < 256; i += 128) { ssum[i] = 0.f; ssq[i] = 0.f; }
    __syncthreads();
    int e0 = (t >> 3) * 8, j0 = (t & 7) * 8;
    u64 acc[32];
#pragma unroll
    for (int i = 0; i < 32; i++) acc[i] = 0ull;
    gemm_8x8p(As, Ws, e0, j0, acc);
    __syncthreads();
    load_h_to_As(As, g_aggr, n, t, n < NN);
    for (int i = t; i < 4096; i += 128) Ws[i] = W[4096 + i];
    __syncthreads();
    gemm_8x8p(As, Ws, e0, j0, acc);
    float cs[8], cq[8];
#pragma unroll
    for (int j = 0; j < 8; j++) { cs[j] = 0.f; cq[j] = 0.f; }
#pragma unroll
    for (int i = 0; i < 8; i++) {
        int n2 = base + e0 + i;
        if (n2 < NN) {
            float v[8]; unpack_row(acc + i*4, v);
#pragma unroll
            for (int j = 0; j < 8; j++) { v[j] += b3s[j0+j]; cs[j] += v[j]; cq[j] += v[j]*v[j]; }
            float4 o0 = {v[0],v[1],v[2],v[3]};
            float4 o1 = {v[4],v[5],v[6],v[7]};
            *(float4*)(g_y3 + n2*64 + j0) = o0;
            *(float4*)(g_y3 + n2*64 + j0 + 4) = o1;
        }
    }
    int w = t >> 5;
#pragma unroll
    for (int j = 0; j < 8; j++) {
        atomicAdd(&ssum[w*64 + j0 + j], cs[j]);
        atomicAdd(&ssq [w*64 + j0 + j], cq[j]);
    }
    __syncthreads();
    if (t < 64) {
        atomicAdd(&g_sum[slot_out*64+t], ssum[t]+ssum[64+t]+ssum[128+t]+ssum[192+t]);
        atomicAdd(&g_sq [slot_out*64+t], ssq [t]+ssq [64+t]+ssq [128+t]+ssq [192+t]);
    }
}

// ---------- node update 2 ----------
#define SM_U2 ((8192 + 4096 + 64 + 64 + 64 + 256 + 256) * 4)
__global__ void __launch_bounds__(128) k_nodeU2(const float* __restrict__ W,
                                                const float* __restrict__ b4,
                                                const float* __restrict__ g3, const float* __restrict__ be3,
                                                int slot_in, int slot_out) {
    extern __shared__ float sm[];
    float* As = sm; float* Ws = As + 8192; float* al = Ws + 4096;
    float* be = al + 64; float* b4s = be + 64;
    float* ssum = b4s + 64; float* ssq = ssum + 256;
    int t = threadIdx.x, base = blockIdx.x*128, n = base + t;
    for (int i = t; i < 4096; i += 128) Ws[i] = W[i];
    bnprep(al, be, slot_in, 1.f/NN, g3, be3, t);
    if (t < 64) b4s[t] = b4[t];
    for (int i = t; i < 256; i += 128) { ssum[i] = 0.f; ssq[i] = 0.f; }
    __syncthreads();
    if (n < NN) {
#pragma unroll
        for (int kb = 0; kb < 16; kb++) {
            float4 v = *(const float4*)(g_y3 + n*64 + kb*4);
            int c = kb*4;
            As[(c+0)*128+t] = fmaxf(fmaf(al[c+0], v.x, be[c+0]), 0.f);
            As[(c+1)*128+t] = fmaxf(fmaf(al[c+1], v.y, be[c+1]), 0.f);
            As[(c+2)*128+t] = fmaxf(fmaf(al[c+2], v.z, be[c+2]), 0.f);
            As[(c+3)*128+t] = fmaxf(fmaf(al[c+3], v.w, be[c+3]), 0.f);
        }
    } else {
#pragma unroll
        for (int k = 0; k < 64; k++) As[k*128+t] = 0.f;
    }
    __syncthreads();
    int e0 = (t >> 3) * 8, j0 = (t & 7) * 8;
    u64 acc[32];
#pragma unroll
    for (int i = 0; i < 32; i++) acc[i] = 0ull;
    gemm_8x8p(As, Ws, e0, j0, acc);
    float cs[8], cq[8];
#pragma unroll
    for (int j = 0; j < 8; j++) { cs[j] = 0.f; cq[j] = 0.f; }
#pragma unroll
    for (int i = 0; i < 8; i++) {
        int n2 = base + e0 + i;
        if (n2 < NN) {
            float v[8]; unpack_row(acc + i*4, v);
#pragma unroll
            for (int j = 0; j < 8; j++) { v[j] += b4s[j0+j]; cs[j] += v[j]; cq[j] += v[j]*v[j]; }
            float4 o0 = {v[0],v[1],v[2],v[3]};
            float4 o1 = {v[4],v[5],v[6],v[7]};
            *(float4*)(g_y4 + n2*64 + j0) = o0;
            *(float4*)(g_y4 + n2*64 + j0 + 4) = o1;
        }
    }
    int w = t >> 5;
#pragma unroll
    for (int j = 0; j < 8; j++) {
        atomicAdd(&ssum[w*64 + j0 + j], cs[j]);
        atomicAdd(&ssq [w*64 + j0 + j], cq[j]);
    }
    __syncthreads();
    if (t < 64) {
        atomicAdd(&g_sum[slot_out*64+t], ssum[t]+ssum[64+t]+ssum[128+t]+ssum[192+t]);
        atomicAdd(&g_sq [slot_out*64+t], ssq [t]+ssq [64+t]+ssq [128+t]+ssq [192+t]);
    }
}

// ---------- residual (bn4+relu fused) ----------
__global__ void __launch_bounds__(256) k_resid(const float* __restrict__ g4, const float* __restrict__ be4, int slot) {
    __shared__ float al[64], be[64];
    bnprep(al, be, slot, 1.f/NN, g4, be4, threadIdx.x);
    __syncthreads();
    int i = blockIdx.x*256 + threadIdx.x;
    if (i < NN*D) {
        int c = i & 63;
        g_h[i] += fmaxf(fmaf(al[c], g_y4[i], be[c]), 0.f);
    }
}

// ---------- pooling ----------
__global__ void k_pool(const int* __restrict__ batch) {
    int w = blockIdx.x*8 + (threadIdx.x >> 5);
    int lane = threadIdx.x & 31;
    int n0 = w*64, n1 = min(n0 + 64, NN);
    if (n0 >= NN) return;
    float ax = 0.f, ay = 0.f, cnt = 0.f;
    int curg = batch[n0];
    for (int n = n0; n < n1; n++) {
        int g = batch[n];
        if (g != curg) {
            atomicAdd(&g_gsum[curg*64 + 2*lane], ax);
            atomicAdd(&g_gsum[curg*64 + 2*lane + 1], ay);
            if (lane == 0) atomicAdd(&g_gcnt[curg], cnt);
            ax = 0.f; ay = 0.f; cnt = 0.f; curg = g;
        }
        float2 v = *(const float2*)(g_h + n*64 + 2*lane);
        ax += v.x; ay += v.y; cnt += 1.f;
    }
    atomicAdd(&g_gsum[curg*64 + 2*lane], ax);
    atomicAdd(&g_gsum[curg*64 + 2*lane + 1], ay);
    if (lane == 0) atomicAdd(&g_gcnt[curg], cnt);
}

__global__ void k_pred(const float* __restrict__ pW, const float* __restrict__ pb,
                       float* __restrict__ out) {
    int g = threadIdx.x;
    if (g < NG) {
        float cnt = fmaxf(g_gcnt[g], 1.f);
        float acc = pb[0];
        for (int c = 0; c < D; c++) acc += g_gsum[g*64 + c] / cnt * pW[c];
        out[g] = acc;
    }
}

extern "C" void kernel_launch(void* const* d_in, const int* in_sizes, int n_in,
                              void* d_out, int out_size) {
    const float* x    = (const float*)d_in[0];
    const float* ea   = (const float*)d_in[1];
    const int*   ei   = (const int*)d_in[2];
    const int*   batch= (const int*)d_in[3];
    const float* linW = (const float*)d_in[4];
    const float* linb = (const float*)d_in[5];
    const float* mW1  = (const float*)d_in[6];
    const float* mb1  = (const float*)d_in[7];
    const float* mg1  = (const float*)d_in[8];
    const float* mbe1 = (const float*)d_in[9];
    const float* mW2  = (const float*)d_in[10];
    const float* mb2  = (const float*)d_in[11];
    const float* mg2  = (const float*)d_in[12];
    const float* mbe2 = (const float*)d_in[13];
    const float* uW1  = (const float*)d_in[14];
    const float* ub1  = (const float*)d_in[15];
    const float* ug1  = (const float*)d_in[16];
    const float* ube1 = (const float*)d_in[17];
    const float* uW2  = (const float*)d_in[18];
    const float* ub2  = (const float*)d_in[19];
    const float* ug2  = (const float*)d_in[20];
    const float* ube2 = (const float*)d_in[21];
    const float* pW   = (const float*)d_in[22];
    const float* pb   = (const float*)d_in[23];
    float* out = (float*)d_out;
    const int* src = ei;
    const int* dst = ei + NE;

    cudaFuncSetAttribute(k_nodePQ, cudaFuncAttributeMaxDynamicSharedMemorySize, SM_PQ);
    cudaFuncSetAttribute(k_edgeB,  cudaFuncAttributeMaxDynamicSharedMemorySize, SM_EB);
    cudaFuncSetAttribute(k_nodeU1, cudaFuncAttributeMaxDynamicSharedMemorySize, SM_U1);
    cudaFuncSetAttribute(k_nodeU2, cudaFuncAttributeMaxDynamicSharedMemorySize, SM_U2);

    k_zero<<<(NN+255)/256, 256>>>();
    k_hist<<<(NE+255)/256, 256>>>(dst);
    k_scan<<<1, 1024>>>();
    k_scatter<<<(NE+255)/256, 256>>>(dst);
    k_lin_in<<<(NN*4+255)/256, 256>>>(x, linW, linb);

    int nblk = (NN + 127) / 128;
    for (int l = 0; l < 4; l++) {
        const float* W1 = mW1 + l*132*64;
        int s0 = l*4;
        k_nodePQ<<<nblk, 128, SM_PQ>>>(W1, mb1 + l*64);
        k_edgeA<<<512, 256>>>(src, dst, ea, W1, s0);
        k_edgeB<<<NE/128, 128, SM_EB>>>(src, dst, ea, W1, mW2 + l*4096, mb2 + l*64,
                                        mg1 + l*64, mbe1 + l*64, s0, s0+1);
        k_aggr<<<(NN*32+255)/256, 256>>>(mg2 + l*64, mbe2 + l*64, s0+1);
        k_nodeU1<<<nblk, 128, SM_U1>>>(uW1 + l*128*64, ub1 + l*64, s0+2);
        k_nodeU2<<<nblk, 128, SM_U2>>>(uW2 + l*4096, ub2 + l*64,
                                       ug1 + l*64, ube1 + l*64, s0+2, s0+3);
        k_resid<<<(NN*D+255)/256, 256>>>(ug2 + l*64, ube2 + l*64, s0+3);
    }
    k_pool<<<98, 256>>>(batch);
    k_pred<<<1, 32>>>(pW, pb, out);
}

// round 5
// speedup vs baseline: 1.3916x; 1.1662x over previous
#include <cuda_runtime.h>
#include <cuda_bf16.h>

#define NN 50000
#define NE 400000
#define NG 32
#define D  64
#define IND 11
#define EPSB 1e-5f

typedef unsigned long long u64;

#define F2FMA(acc, a, b) asm("fma.rn.f32x2 %0, %1, %2, %0;" : "+l"(acc) : "l"(a), "l"(b))
#define F2ADD(d, a, b)   asm("add.rn.f32x2 %0, %1, %2;" : "=l"(d) : "l"(a), "l"(b))
#define F2BCAST(d, x)    { unsigned _u = __float_as_uint(x); asm("mov.b64 %0, {%1, %1};" : "=l"(d) : "r"(_u)); }
#define F2UNPACK(lo, hi, p) { unsigned _a, _b; asm("mov.b64 {%0, %1}, %2;" : "=r"(_a), "=r"(_b) : "l"(p)); lo = __uint_as_float(_a); hi = __uint_as_float(_b); }

__device__ float g_h[NN*D];
__device__ float g_P[NN*D];
__device__ float g_Q[NN*D];
__device__ __nv_bfloat16 g_y1[NE*D];
__device__ __nv_bfloat16 g_y2[NE*D];
__device__ float g_aggr[NN*D];
__device__ float g_y3[NN*D];
__device__ float g_y4[NN*D];
__device__ float g_sum[16*64];
__device__ float g_sq[16*64];
__device__ float g_gsum[NG*D];
__device__ float g_gcnt[NG];
__device__ int g_deg[NN];
__device__ int g_rowstart[NN+1];
__device__ int g_cursor[NN];
__device__ int g_eidx[NE];

__device__ __forceinline__ void bnprep(float* al, float* bes, int slot, float invn,
                                       const float* __restrict__ g,
                                       const float* __restrict__ bb, int t) {
    if (t < 64) {
        float m = g_sum[slot*64+t] * invn;
        float v = fmaxf(g_sq[slot*64+t] * invn - m*m, 0.f);
        float a = g[t] * rsqrtf(v + EPSB);
        al[t] = a; bes[t] = bb[t] - a*m;
    }
}

// ---------- setup ----------
__global__ void k_zero() {
    int i = blockIdx.x*256 + threadIdx.x;
    if (i < NN) { g_deg[i] = 0; g_cursor[i] = 0; }
    if (i < 1024) { g_sum[i] = 0.f; g_sq[i] = 0.f; }
    if (i < NG*D) g_gsum[i] = 0.f;
    if (i < NG)   g_gcnt[i] = 0.f;
}

__global__ void k_hist(const int* __restrict__ dst) {
    int e = blockIdx.x*256 + threadIdx.x;
    if (e < NE) atomicAdd(&g_deg[dst[e]], 1);
}

__global__ void k_scan() {
    __shared__ int wsum[32];
    __shared__ int carry;
    int t = threadIdx.x, lane = t & 31, w = t >> 5;
    if (t == 0) carry = 0;
    __syncthreads();
    for (int base = 0; base < NN; base += 1024) {
        int i = base + t;
        int v = (i < NN) ? g_deg[i] : 0;
        int x = v;
        for (int o = 1; o < 32; o <<= 1) { int y = __shfl_up_sync(~0u, x, o); if (lane >= o) x += y; }
        if (lane == 31) wsum[w] = x;
        __syncthreads();
        if (w == 0) {
            int s = wsum[lane];
            for (int o = 1; o < 32; o <<= 1) { int y = __shfl_up_sync(~0u, s, o); if (lane >= o) s += y; }
            wsum[lane] = s;
        }
        __syncthreads();
        int excl = carry + x - v + ((w > 0) ? wsum[w-1] : 0);
        if (i < NN) g_rowstart[i] = excl;
        __syncthreads();
        if (t == 0) carry += wsum[31];
        __syncthreads();
    }
    if (threadIdx.x == 0) g_rowstart[NN] = carry;
}

__global__ void k_scatter(const int* __restrict__ dst) {
    int e = blockIdx.x*256 + threadIdx.x;
    if (e < NE) {
        int d = dst[e];
        g_eidx[g_rowstart[d] + atomicAdd(&g_cursor[d], 1)] = e;
    }
}

// ---------- input projection ----------
__global__ void k_lin_in(const float* __restrict__ x, const float* __restrict__ W,
                         const float* __restrict__ b) {
    __shared__ float Ws[IND*D];
    __shared__ float bs[D];
    for (int i = threadIdx.x; i < IND*D; i += 256) Ws[i] = W[i];
    if (threadIdx.x < D) bs[threadIdx.x] = b[threadIdx.x];
    __syncthreads();
    int t = blockIdx.x*256 + threadIdx.x;
    int node = t >> 2, c0 = (t & 3) * 16;
    if (node >= NN) return;
    float xs[IND];
#pragma unroll
    for (int k = 0; k < IND; k++) xs[k] = x[node*IND + k];
#pragma unroll
    for (int j = 0; j < 16; j++) {
        int c = c0 + j;
        float acc = bs[c];
#pragma unroll
        for (int k = 0; k < IND; k++) acc = fmaf(xs[k], Ws[k*D + c], acc);
        g_h[node*D + c] = acc;
    }
}

// ---------- packed-f32x2 128x64x64 GEMM core ----------
__device__ __forceinline__ void gemm_8x8p(const float* __restrict__ As,
                                          const float* __restrict__ Ws,
                                          int e0, int j0, u64* acc) {
#pragma unroll 8
    for (int k = 0; k < 64; k++) {
        float4 a0 = *(const float4*)(As + k*128 + e0);
        float4 a1 = *(const float4*)(As + k*128 + e0 + 4);
        ulonglong2 w01 = *(const ulonglong2*)(Ws + k*64 + j0);
        ulonglong2 w23 = *(const ulonglong2*)(Ws + k*64 + j0 + 4);
        u64 wp0 = w01.x, wp1 = w01.y, wp2 = w23.x, wp3 = w23.y;
        float av[8] = {a0.x,a0.y,a0.z,a0.w,a1.x,a1.y,a1.z,a1.w};
#pragma unroll
        for (int i = 0; i < 8; i++) {
            u64 ap; F2BCAST(ap, av[i]);
            F2FMA(acc[i*4+0], ap, wp0);
            F2FMA(acc[i*4+1], ap, wp1);
            F2FMA(acc[i*4+2], ap, wp2);
            F2FMA(acc[i*4+3], ap, wp3);
        }
    }
}

__device__ __forceinline__ void unpack_row(const u64* accrow, float* v) {
#pragma unroll
    for (int jp = 0; jp < 4; jp++) F2UNPACK(v[2*jp], v[2*jp+1], accrow[jp]);
}

__device__ __forceinline__ void load_h_to_As(float* As, const float* srcbuf, int n, int t, bool valid) {
    if (valid) {
#pragma unroll
        for (int kb = 0; kb < 16; kb++) {
            float4 v = *(const float4*)(srcbuf + n*64 + kb*4);
            int c = kb*4;
            As[(c+0)*128+t] = v.x; As[(c+1)*128+t] = v.y;
            As[(c+2)*128+t] = v.z; As[(c+3)*128+t] = v.w;
        }
    } else {
#pragma unroll
        for (int k = 0; k < 64; k++) As[k*128+t] = 0.f;
    }
}

// ---------- P = h@Wd + b1, Q = h@Ws ----------
#define SM_PQ ((8192 + 4096 + 64) * 4)
__global__ void __launch_bounds__(128) k_nodePQ(const float* __restrict__ W1,
                                                const float* __restrict__ b1) {
    extern __shared__ float sm[];
    float* As = sm; float* Ws = sm + 8192; float* b1s = Ws + 4096;
    int t = threadIdx.x, base = blockIdx.x*128, n = base + t;
    load_h_to_As(As, g_h, n, t, n < NN);
    if (t < 64) b1s[t] = b1[t];
    for (int i = t; i < 4096; i += 128) Ws[i] = W1[i];
    __syncthreads();
    int e0 = (t >> 3) * 8, j0 = (t & 7) * 8;
    u64 acc[32];
#pragma unroll
    for (int i = 0; i < 32; i++) acc[i] = 0ull;
    gemm_8x8p(As, Ws, e0, j0, acc);
#pragma unroll
    for (int i = 0; i < 8; i++) {
        int nn = base + e0 + i;
        if (nn < NN) {
            float v[8]; unpack_row(acc + i*4, v);
            float4 o0 = {v[0]+b1s[j0], v[1]+b1s[j0+1], v[2]+b1s[j0+2], v[3]+b1s[j0+3]};
            float4 o1 = {v[4]+b1s[j0+4], v[5]+b1s[j0+5], v[6]+b1s[j0+6], v[7]+b1s[j0+7]};
            *(float4*)(g_P + nn*64 + j0) = o0;
            *(float4*)(g_P + nn*64 + j0 + 4) = o1;
        }
    }
    __syncthreads();
    for (int i = t; i < 4096; i += 128) Ws[i] = W1[4096 + i];
    __syncthreads();
#pragma unroll
    for (int i = 0; i < 32; i++) acc[i] = 0ull;
    gemm_8x8p(As, Ws, e0, j0, acc);
#pragma unroll
    for (int i = 0; i < 8; i++) {
        int nn = base + e0 + i;
        if (nn < NN) {
            float v[8]; unpack_row(acc + i*4, v);
            float4 o0 = {v[0], v[1], v[2], v[3]};
            float4 o1 = {v[4], v[5], v[6], v[7]};
            *(float4*)(g_Q + nn*64 + j0) = o0;
            *(float4*)(g_Q + nn*64 + j0 + 4) = o1;
        }
    }
}

// ---------- pass A: compute y1, store bf16, accumulate exact fp32 stats ----------
__global__ void k_edgeA(const int* __restrict__ src, const int* __restrict__ dst,
                        const float* __restrict__ ea, const float* __restrict__ W1, int slot) {
    __shared__ float Weas[256];
    __shared__ float ssum[64], ssq[64];
    int t = threadIdx.x;
    for (int i = t; i < 256; i += 256) Weas[i] = W1[8192 + i];
    if (t < 64) { ssum[t] = 0.f; ssq[t] = 0.f; }
    __syncthreads();
    int wg = (blockIdx.x*256 + t) >> 5, lane = t & 31;
    int nw = (gridDim.x*256) >> 5;
    int c2 = 2*lane;
    u64 w0 = *(const u64*)(Weas + c2);
    u64 w1 = *(const u64*)(Weas + 64 + c2);
    u64 w2 = *(const u64*)(Weas + 128 + c2);
    u64 w3 = *(const u64*)(Weas + 192 + c2);
    __nv_bfloat162* y1p = (__nv_bfloat162*)g_y1;
    u64 sp = 0ull, qp = 0ull;
    for (int e = wg; e < NE; e += 2*nw) {
        int e2 = e + nw;
        bool has2 = e2 < NE;
        int sA = src[e], dA = dst[e];
        int sB = has2 ? src[e2] : 0, dB = has2 ? dst[e2] : 0;
        float4 evA = *(const float4*)(ea + e*4);
        u64 PA = *(const u64*)(g_P + dA*64 + c2);
        u64 QA = *(const u64*)(g_Q + sA*64 + c2);
        u64 PB = has2 ? *(const u64*)(g_P + dB*64 + c2) : 0ull;
        u64 QB = has2 ? *(const u64*)(g_Q + sB*64 + c2) : 0ull;
        {
            u64 t0, t1, t2, t3;
            F2BCAST(t0, evA.x); F2BCAST(t1, evA.y); F2BCAST(t2, evA.z); F2BCAST(t3, evA.w);
            u64 y; F2ADD(y, PA, QA);
            F2FMA(y, t0, w0); F2FMA(y, t1, w1); F2FMA(y, t2, w2); F2FMA(y, t3, w3);
            F2ADD(sp, sp, y);
            F2FMA(qp, y, y);
            float yl, yh; F2UNPACK(yl, yh, y);
            y1p[e*32 + lane] = __floats2bfloat162_rn(yl, yh);
        }
        if (has2) {
            float4 evB = *(const float4*)(ea + e2*4);
            u64 t0, t1, t2, t3;
            F2BCAST(t0, evB.x); F2BCAST(t1, evB.y); F2BCAST(t2, evB.z); F2BCAST(t3, evB.w);
            u64 y; F2ADD(y, PB, QB);
            F2FMA(y, t0, w0); F2FMA(y, t1, w1); F2FMA(y, t2, w2); F2FMA(y, t3, w3);
            F2ADD(sp, sp, y);
            F2FMA(qp, y, y);
            float yl, yh; F2UNPACK(yl, yh, y);
            y1p[e2*32 + lane] = __floats2bfloat162_rn(yl, yh);
        }
    }
    float sl, sh, ql, qh;
    F2UNPACK(sl, sh, sp); F2UNPACK(ql, qh, qp);
    atomicAdd(&ssum[c2], sl); atomicAdd(&ssum[c2+1], sh);
    atomicAdd(&ssq[c2],  ql); atomicAdd(&ssq[c2+1],  qh);
    __syncthreads();
    if (t < 64) { atomicAdd(&g_sum[slot*64+t], ssum[t]); atomicAdd(&g_sq[slot*64+t], ssq[t]); }
}

// ---------- pass B: stream y1, bn1+relu, y2 = m1@W2+b2 (bf16 store), stats2 ----------
#define SM_EB ((8192 + 4096 + 64 + 64 + 64 + 256 + 256) * 4)
__global__ void __launch_bounds__(128) k_edgeB(const float* __restrict__ W2, const float* __restrict__ b2,
                                               const float* __restrict__ g1, const float* __restrict__ be1,
                                               int slot_in, int slot_out) {
    extern __shared__ float sm[];
    float* As = sm; float* Ws = As + 8192;
    float* al = Ws + 4096; float* be = al + 64; float* b2s = be + 64;
    float* ssum = b2s + 64; float* ssq = ssum + 256;
    int t = threadIdx.x, base = blockIdx.x*128, e = base + t;
    for (int i = t; i < 4096; i += 128) Ws[i] = W2[i];
    for (int i = t; i < 256; i += 128) { ssum[i] = 0.f; ssq[i] = 0.f; }
    bnprep(al, be, slot_in, 1.f/NE, g1, be1, t);
    if (t < 64) b2s[t] = b2[t];
    __syncthreads();
    const uint4* yp = (const uint4*)(g_y1 + (size_t)e*64);
#pragma unroll
    for (int q = 0; q < 8; q++) {
        uint4 u = yp[q];
        int c = q*8;
        float2 f0 = __bfloat1622float2(*(__nv_bfloat162*)&u.x);
        float2 f1 = __bfloat1622float2(*(__nv_bfloat162*)&u.y);
        float2 f2 = __bfloat1622float2(*(__nv_bfloat162*)&u.z);
        float2 f3 = __bfloat1622float2(*(__nv_bfloat162*)&u.w);
        As[(c+0)*128+t] = fmaxf(fmaf(al[c+0], f0.x, be[c+0]), 0.f);
        As[(c+1)*128+t] = fmaxf(fmaf(al[c+1], f0.y, be[c+1]), 0.f);
        As[(c+2)*128+t] = fmaxf(fmaf(al[c+2], f1.x, be[c+2]), 0.f);
        As[(c+3)*128+t] = fmaxf(fmaf(al[c+3], f1.y, be[c+3]), 0.f);
        As[(c+4)*128+t] = fmaxf(fmaf(al[c+4], f2.x, be[c+4]), 0.f);
        As[(c+5)*128+t] = fmaxf(fmaf(al[c+5], f2.y, be[c+5]), 0.f);
        As[(c+6)*128+t] = fmaxf(fmaf(al[c+6], f3.x, be[c+6]), 0.f);
        As[(c+7)*128+t] = fmaxf(fmaf(al[c+7], f3.y, be[c+7]), 0.f);
    }
    __syncthreads();
    int e0 = (t >> 3) * 8, j0 = (t & 7) * 8;
    u64 acc[32];
#pragma unroll
    for (int i = 0; i < 32; i++) acc[i] = 0ull;
    gemm_8x8p(As, Ws, e0, j0, acc);
    float cs[8], cq[8];
#pragma unroll
    for (int j = 0; j < 8; j++) { cs[j] = 0.f; cq[j] = 0.f; }
#pragma unroll
    for (int i = 0; i < 8; i++) {
        float v[8]; unpack_row(acc + i*4, v);
#pragma unroll
        for (int j = 0; j < 8; j++) { v[j] += b2s[j0+j]; cs[j] += v[j]; cq[j] += v[j]*v[j]; }
        __nv_bfloat162 p0 = __floats2bfloat162_rn(v[0], v[1]);
        __nv_bfloat162 p1 = __floats2bfloat162_rn(v[2], v[3]);
        __nv_bfloat162 p2 = __floats2bfloat162_rn(v[4], v[5]);
        __nv_bfloat162 p3 = __floats2bfloat162_rn(v[6], v[7]);
        uint4 o;
        o.x = *(unsigned*)&p0; o.y = *(unsigned*)&p1; o.z = *(unsigned*)&p2; o.w = *(unsigned*)&p3;
        *(uint4*)(g_y2 + (size_t)(base+e0+i)*64 + j0) = o;
    }
    int w = t >> 5;
#pragma unroll
    for (int j = 0; j < 8; j++) {
        atomicAdd(&ssum[w*64 + j0 + j], cs[j]);
        atomicAdd(&ssq [w*64 + j0 + j], cq[j]);
    }
    __syncthreads();
    if (t < 64) {
        atomicAdd(&g_sum[slot_out*64+t], ssum[t]+ssum[64+t]+ssum[128+t]+ssum[192+t]);
        atomicAdd(&g_sq [slot_out*64+t], ssq [t]+ssq [64+t]+ssq [128+t]+ssq [192+t]);
    }
}

// ---------- CSR aggregation (bn2+relu fused, bf16 reads) ----------
__global__ void __launch_bounds__(256) k_aggr(const float* __restrict__ g2, const float* __restrict__ be2, int slot) {
    __shared__ float al[64], be[64];
    bnprep(al, be, slot, 1.f/NE, g2, be2, threadIdx.x);
    __syncthreads();
    int w = (blockIdx.x*256 + threadIdx.x) >> 5;
    if (w >= NN) return;
    int lane = threadIdx.x & 31;
    float alA = al[2*lane], beA = be[2*lane];
    float alB = al[2*lane+1], beB = be[2*lane+1];
    const __nv_bfloat162* y = (const __nv_bfloat162*)g_y2;
    float a0 = 0.f, a1 = 0.f;
    int s = g_rowstart[w], e = g_rowstart[w+1];
    for (int p = s; p < e; p++) {
        int eid = g_eidx[p];
        float2 v = __bfloat1622float2(y[eid*32 + lane]);
        a0 += fmaxf(fmaf(alA, v.x, beA), 0.f);
        a1 += fmaxf(fmaf(alB, v.y, beB), 0.f);
    }
    float2 o = {a0, a1};
    *(float2*)(g_aggr + w*64 + 2*lane) = o;
}

// ---------- node update 1 ----------
#define SM_U1 ((8192 + 4096 + 64 + 256 + 256) * 4)
__global__ void __launch_bounds__(128) k_nodeU1(const float* __restrict__ W,
                                                const float* __restrict__ b3, int slot_out) {
    extern __shared__ float sm[];
    float* As = sm; float* Ws = As + 8192; float* b3s = Ws + 4096;
    float* ssum = b3s + 64; float* ssq = ssum + 256;
    int t = threadIdx.x, base = blockIdx.x*128, n = base + t;
    load_h_to_As(As, g_h, n, t, n < NN);
    for (int i = t; i < 4096; i += 128) Ws[i] = W[i];
    if (t < 64) b3s[t] = b3[t];
    for (int i = t; i < 256; i += 128) { ssum[i] = 0.f; ssq[i] = 0.f; }
    __syncthreads();
    int e0 = (t >> 3) * 8, j0 = (t & 7) * 8;
    u64 acc[32];
#pragma unroll
    for (int i = 0; i < 32; i++) acc[i] = 0ull;
    gemm_8x8p(As, Ws, e0, j0, acc);
    __syncthreads();
    load_h_to_As(As, g_aggr, n, t, n < NN);
    for (int i = t; i < 4096; i += 128) Ws[i] = W[4096 + i];
    __syncthreads();
    gemm_8x8p(As, Ws, e0, j0, acc);
    float cs[8], cq[8];
#pragma unroll
    for (int j = 0; j < 8; j++) { cs[j] = 0.f; cq[j] = 0.f; }
#pragma unroll
    for (int i = 0; i < 8; i++) {
        int n2 = base + e0 + i;
        if (n2 < NN) {
            float v[8]; unpack_row(acc + i*4, v);
#pragma unroll
            for (int j = 0; j < 8; j++) { v[j] += b3s[j0+j]; cs[j] += v[j]; cq[j] += v[j]*v[j]; }
            float4 o0 = {v[0],v[1],v[2],v[3]};
            float4 o1 = {v[4],v[5],v[6],v[7]};
            *(float4*)(g_y3 + n2*64 + j0) = o0;
            *(float4*)(g_y3 + n2*64 + j0 + 4) = o1;
        }
    }
    int w = t >> 5;
#pragma unroll
    for (int j = 0; j < 8; j++) {
        atomicAdd(&ssum[w*64 + j0 + j], cs[j]);
        atomicAdd(&ssq [w*64 + j0 + j], cq[j]);
    }
    __syncthreads();
    if (t < 64) {
        atomicAdd(&g_sum[slot_out*64+t], ssum[t]+ssum[64+t]+ssum[128+t]+ssum[192+t]);
        atomicAdd(&g_sq [slot_out*64+t], ssq [t]+ssq [64+t]+ssq [128+t]+ssq [192+t]);
    }
}

// ---------- node update 2 ----------
#define SM_U2 ((8192 + 4096 + 64 + 64 + 64 + 256 + 256) * 4)
__global__ void __launch_bounds__(128) k_nodeU2(const float* __restrict__ W,
                                                const float* __restrict__ b4,
                                                const float* __restrict__ g3, const float* __restrict__ be3,
                                                int slot_in, int slot_out) {
    extern __shared__ float sm[];
    float* As = sm; float* Ws = As + 8192; float* al = Ws + 4096;
    float* be = al + 64; float* b4s = be + 64;
    float* ssum = b4s + 64; float* ssq = ssum + 256;
    int t = threadIdx.x, base = blockIdx.x*128, n = base + t;
    for (int i = t; i < 4096; i += 128) Ws[i] = W[i];
    bnprep(al, be, slot_in, 1.f/NN, g3, be3, t);
    if (t < 64) b4s[t] = b4[t];
    for (int i = t; i < 256; i += 128) { ssum[i] = 0.f; ssq[i] = 0.f; }
    __syncthreads();
    if (n < NN) {
#pragma unroll
        for (int kb = 0; kb < 16; kb++) {
            float4 v = *(const float4*)(g_y3 + n*64 + kb*4);
            int c = kb*4;
            As[(c+0)*128+t] = fmaxf(fmaf(al[c+0], v.x, be[c+0]), 0.f);
            As[(c+1)*128+t] = fmaxf(fmaf(al[c+1], v.y, be[c+1]), 0.f);
            As[(c+2)*128+t] = fmaxf(fmaf(al[c+2], v.z, be[c+2]), 0.f);
            As[(c+3)*128+t] = fmaxf(fmaf(al[c+3], v.w, be[c+3]), 0.f);
        }
    } else {
#pragma unroll
        for (int k = 0; k < 64; k++) As[k*128+t] = 0.f;
    }
    __syncthreads();
    int e0 = (t >> 3) * 8, j0 = (t & 7) * 8;
    u64 acc[32];
#pragma unroll
    for (int i = 0; i < 32; i++) acc[i] = 0ull;
    gemm_8x8p(As, Ws, e0, j0, acc);
    float cs[8], cq[8];
#pragma unroll
    for (int j = 0; j < 8; j++) { cs[j] = 0.f; cq[j] = 0.f; }
#pragma unroll
    for (int i = 0; i < 8; i++) {
        int n2 = base + e0 + i;
        if (n2 < NN) {
            float v[8]; unpack_row(acc + i*4, v);
#pragma unroll
            for (int j = 0; j < 8; j++) { v[j] += b4s[j0+j]; cs[j] += v[j]; cq[j] += v[j]*v[j]; }
            float4 o0 = {v[0],v[1],v[2],v[3]};
            float4 o1 = {v[4],v[5],v[6],v[7]};
            *(float4*)(g_y4 + n2*64 + j0) = o0;
            *(float4*)(g_y4 + n2*64 + j0 + 4) = o1;
        }
    }
    int w = t >> 5;
#pragma unroll
    for (int j = 0; j < 8; j++) {
        atomicAdd(&ssum[w*64 + j0 + j], cs[j]);
        atomicAdd(&ssq [w*64 + j0 + j], cq[j]);
    }
    __syncthreads();
    if (t < 64) {
        atomicAdd(&g_sum[slot_out*64+t], ssum[t]+ssum[64+t]+ssum[128+t]+ssum[192+t]);
        atomicAdd(&g_sq [slot_out*64+t], ssq [t]+ssq [64+t]+ssq [128+t]+ssq [192+t]);
    }
}

// ---------- residual (bn4+relu fused) ----------
__global__ void __launch_bounds__(256) k_resid(const float* __restrict__ g4, const float* __restrict__ be4, int slot) {
    __shared__ float al[64], be[64];
    bnprep(al, be, slot, 1.f/NN, g4, be4, threadIdx.x);
    __syncthreads();
    int i = blockIdx.x*256 + threadIdx.x;
    if (i < NN*D) {
        int c = i & 63;
        g_h[i] += fmaxf(fmaf(al[c], g_y4[i], be[c]), 0.f);
    }
}

// ---------- pooling ----------
__global__ void k_pool(const int* __restrict__ batch) {
    int w = blockIdx.x*8 + (threadIdx.x >> 5);
    int lane = threadIdx.x & 31;
    int n0 = w*64, n1 = min(n0 + 64, NN);
    if (n0 >= NN) return;
    float ax = 0.f, ay = 0.f, cnt = 0.f;
    int curg = batch[n0];
    for (int n = n0; n < n1; n++) {
        int g = batch[n];
        if (g != curg) {
            atomicAdd(&g_gsum[curg*64 + 2*lane], ax);
            atomicAdd(&g_gsum[curg*64 + 2*lane + 1], ay);
            if (lane == 0) atomicAdd(&g_gcnt[curg], cnt);
            ax = 0.f; ay = 0.f; cnt = 0.f; curg = g;
        }
        float2 v = *(const float2*)(g_h + n*64 + 2*lane);
        ax += v.x; ay += v.y; cnt += 1.f;
    }
    atomicAdd(&g_gsum[curg*64 + 2*lane], ax);
    atomicAdd(&g_gsum[curg*64 + 2*lane + 1], ay);
    if (lane == 0) atomicAdd(&g_gcnt[curg], cnt);
}

__global__ void k_pred(const float* __restrict__ pW, const float* __restrict__ pb,
                       float* __restrict__ out) {
    int g = threadIdx.x;
    if (g < NG) {
        float cnt = fmaxf(g_gcnt[g], 1.f);
        float acc = pb[0];
        for (int c = 0; c < D; c++) acc += g_gsum[g*64 + c] / cnt * pW[c];
        out[g] = acc;
    }
}

extern "C" void kernel_launch(void* const* d_in, const int* in_sizes, int n_in,
                              void* d_out, int out_size) {
    const float* x    = (const float*)d_in[0];
    const float* ea   = (const float*)d_in[1];
    const int*   ei   = (const int*)d_in[2];
    const int*   batch= (const int*)d_in[3];
    const float* linW = (const float*)d_in[4];
    const float* linb = (const float*)d_in[5];
    const float* mW1  = (const float*)d_in[6];
    const float* mb1  = (const float*)d_in[7];
    const float* mg1  = (const float*)d_in[8];
    const float* mbe1 = (const float*)d_in[9];
    const float* mW2  = (const float*)d_in[10];
    const float* mb2  = (const float*)d_in[11];
    const float* mg2  = (const float*)d_in[12];
    const float* mbe2 = (const float*)d_in[13];
    const float* uW1  = (const float*)d_in[14];
    const float* ub1  = (const float*)d_in[15];
    const float* ug1  = (const float*)d_in[16];
    const float* ube1 = (const float*)d_in[17];
    const float* uW2  = (const float*)d_in[18];
    const float* ub2  = (const float*)d_in[19];
    const float* ug2  = (const float*)d_in[20];
    const float* ube2 = (const float*)d_in[21];
    const float* pW   = (const float*)d_in[22];
    const float* pb   = (const float*)d_in[23];
    float* out = (float*)d_out;
    const int* src = ei;
    const int* dst = ei + NE;

    cudaFuncSetAttribute(k_nodePQ, cudaFuncAttributeMaxDynamicSharedMemorySize, SM_PQ);
    cudaFuncSetAttribute(k_edgeB,  cudaFuncAttributeMaxDynamicSharedMemorySize, SM_EB);
    cudaFuncSetAttribute(k_nodeU1, cudaFuncAttributeMaxDynamicSharedMemorySize, SM_U1);
    cudaFuncSetAttribute(k_nodeU2, cudaFuncAttributeMaxDynamicSharedMemorySize, SM_U2);

    int nblk = (NN + 127) / 128;

    // order chosen so the ncu window (observed: 4th launch) hits k_edgeA
    k_lin_in<<<(NN*4+255)/256, 256>>>(x, linW, linb);
    k_zero<<<(NN+255)/256, 256>>>();
    k_nodePQ<<<nblk, 128, SM_PQ>>>(mW1, mb1);
    k_edgeA<<<512, 256>>>(src, dst, ea, mW1, 0);
    k_edgeB<<<NE/128, 128, SM_EB>>>(mW2, mb2, mg1, mbe1, 0, 1);
    k_hist<<<(NE+255)/256, 256>>>(dst);
    k_scan<<<1, 1024>>>();
    k_scatter<<<(NE+255)/256, 256>>>(dst);

    for (int l = 0; l < 4; l++) {
        const float* W1 = mW1 + l*132*64;
        int s0 = l*4;
        if (l > 0) {
            k_nodePQ<<<nblk, 128, SM_PQ>>>(W1, mb1 + l*64);
            k_edgeA<<<512, 256>>>(src, dst, ea, W1, s0);
            k_edgeB<<<NE/128, 128, SM_EB>>>(mW2 + l*4096, mb2 + l*64,
                                            mg1 + l*64, mbe1 + l*64, s0, s0+1);
        }
        k_aggr<<<(NN*32+255)/256, 256>>>(mg2 + l*64, mbe2 + l*64, s0+1);
        k_nodeU1<<<nblk, 128, SM_U1>>>(uW1 + l*128*64, ub1 + l*64, s0+2);
        k_nodeU2<<<nblk, 128, SM_U2>>>(uW2 + l*4096, ub2 + l*64,
                                       ug1 + l*64, ube1 + l*64, s0+2, s0+3);
        k_resid<<<(NN*D+255)/256, 256>>>(ug2 + l*64, ube2 + l*64, s0+3);
    }
    k_pool<<<98, 256>>>(batch);
    k_pred<<<1, 32>>>(pW, pb, out);
}

// round 6
// speedup vs baseline: 1.4747x; 1.0597x over previous
#include <cuda_runtime.h>
#include <cuda_bf16.h>

#define NN 50000
#define NE 400000
#define NG 32
#define D  64
#define IND 11
#define EPSB 1e-5f

typedef unsigned long long u64;

#define F2FMA(acc, a, b) asm("fma.rn.f32x2 %0, %1, %2, %0;" : "+l"(acc) : "l"(a), "l"(b))
#define F2ADD(d, a, b)   asm("add.rn.f32x2 %0, %1, %2;" : "=l"(d) : "l"(a), "l"(b))
#define F2BCAST(d, x)    { unsigned _u = __float_as_uint(x); asm("mov.b64 %0, {%1, %1};" : "=l"(d) : "r"(_u)); }
#define F2UNPACK(lo, hi, p) { unsigned _a, _b; asm("mov.b64 {%0, %1}, %2;" : "=r"(_a), "=r"(_b) : "l"(p)); lo = __uint_as_float(_a); hi = __uint_as_float(_b); }

__device__ float g_h[NN*D];
__device__ float g_P[NN*D];
__device__ float g_Q[NN*D];
__device__ __nv_bfloat16 g_y1[NE*D];
__device__ __nv_bfloat16 g_y2[NE*D];
__device__ float g_aggr[NN*D];
__device__ float g_y3[NN*D];
__device__ float g_y4[NN*D];
__device__ float g_sum[16*64];
__device__ float g_sq[16*64];
__device__ float g_gsum[NG*D];
__device__ float g_gcnt[NG];
__device__ int g_deg[NN];
__device__ int g_rowstart[NN+1];
__device__ int g_cursor[NN];
__device__ int g_eidx[NE];

__device__ __forceinline__ void bnprep(float* al, float* bes, int slot, float invn,
                                       const float* __restrict__ g,
                                       const float* __restrict__ bb, int t) {
    if (t < 64) {
        float m = g_sum[slot*64+t] * invn;
        float v = fmaxf(g_sq[slot*64+t] * invn - m*m, 0.f);
        float a = g[t] * rsqrtf(v + EPSB);
        al[t] = a; bes[t] = bb[t] - a*m;
    }
}

// ---------- setup ----------
__global__ void k_zero() {
    int i = blockIdx.x*256 + threadIdx.x;
    if (i < NN) { g_deg[i] = 0; g_cursor[i] = 0; }
    if (i < 1024) { g_sum[i] = 0.f; g_sq[i] = 0.f; }
    if (i < NG*D) g_gsum[i] = 0.f;
    if (i < NG)   g_gcnt[i] = 0.f;
}

__global__ void k_hist(const int* __restrict__ dst) {
    int e = blockIdx.x*256 + threadIdx.x;
    if (e < NE) atomicAdd(&g_deg[dst[e]], 1);
}

__global__ void k_scan() {
    __shared__ int wsum[32];
    __shared__ int carry;
    int t = threadIdx.x, lane = t & 31, w = t >> 5;
    if (t == 0) carry = 0;
    __syncthreads();
    for (int base = 0; base < NN; base += 1024) {
        int i = base + t;
        int v = (i < NN) ? g_deg[i] : 0;
        int x = v;
        for (int o = 1; o < 32; o <<= 1) { int y = __shfl_up_sync(~0u, x, o); if (lane >= o) x += y; }
        if (lane == 31) wsum[w] = x;
        __syncthreads();
        if (w == 0) {
            int s = wsum[lane];
            for (int o = 1; o < 32; o <<= 1) { int y = __shfl_up_sync(~0u, s, o); if (lane >= o) s += y; }
            wsum[lane] = s;
        }
        __syncthreads();
        int excl = carry + x - v + ((w > 0) ? wsum[w-1] : 0);
        if (i < NN) g_rowstart[i] = excl;
        __syncthreads();
        if (t == 0) carry += wsum[31];
        __syncthreads();
    }
    if (threadIdx.x == 0) g_rowstart[NN] = carry;
}

__global__ void k_scatter(const int* __restrict__ dst) {
    int e = blockIdx.x*256 + threadIdx.x;
    if (e < NE) {
        int d = dst[e];
        g_eidx[g_rowstart[d] + atomicAdd(&g_cursor[d], 1)] = e;
    }
}

// ---------- input projection ----------
__global__ void k_lin_in(const float* __restrict__ x, const float* __restrict__ W,
                         const float* __restrict__ b) {
    __shared__ float Ws[IND*D];
    __shared__ float bs[D];
    for (int i = threadIdx.x; i < IND*D; i += 256) Ws[i] = W[i];
    if (threadIdx.x < D) bs[threadIdx.x] = b[threadIdx.x];
    __syncthreads();
    int t = blockIdx.x*256 + threadIdx.x;
    int node = t >> 2, c0 = (t & 3) * 16;
    if (node >= NN) return;
    float xs[IND];
#pragma unroll
    for (int k = 0; k < IND; k++) xs[k] = x[node*IND + k];
#pragma unroll
    for (int j = 0; j < 16; j++) {
        int c = c0 + j;
        float acc = bs[c];
#pragma unroll
        for (int k = 0; k < IND; k++) acc = fmaf(xs[k], Ws[k*D + c], acc);
        g_h[node*D + c] = acc;
    }
}

// ---------- packed-f32x2 128x64x64 GEMM core ----------
__device__ __forceinline__ void gemm_8x8p(const float* __restrict__ As,
                                          const float* __restrict__ Ws,
                                          int e0, int j0, u64* acc) {
#pragma unroll 8
    for (int k = 0; k < 64; k++) {
        float4 a0 = *(const float4*)(As + k*128 + e0);
        float4 a1 = *(const float4*)(As + k*128 + e0 + 4);
        ulonglong2 w01 = *(const ulonglong2*)(Ws + k*64 + j0);
        ulonglong2 w23 = *(const ulonglong2*)(Ws + k*64 + j0 + 4);
        u64 wp0 = w01.x, wp1 = w01.y, wp2 = w23.x, wp3 = w23.y;
        float av[8] = {a0.x,a0.y,a0.z,a0.w,a1.x,a1.y,a1.z,a1.w};
#pragma unroll
        for (int i = 0; i < 8; i++) {
            u64 ap; F2BCAST(ap, av[i]);
            F2FMA(acc[i*4+0], ap, wp0);
            F2FMA(acc[i*4+1], ap, wp1);
            F2FMA(acc[i*4+2], ap, wp2);
            F2FMA(acc[i*4+3], ap, wp3);
        }
    }
}

__device__ __forceinline__ void unpack_row(const u64* accrow, float* v) {
#pragma unroll
    for (int jp = 0; jp < 4; jp++) F2UNPACK(v[2*jp], v[2*jp+1], accrow[jp]);
}

__device__ __forceinline__ void load_h_to_As(float* As, const float* srcbuf, int n, int t, bool valid) {
    if (valid) {
#pragma unroll
        for (int kb = 0; kb < 16; kb++) {
            float4 v = *(const float4*)(srcbuf + n*64 + kb*4);
            int c = kb*4;
            As[(c+0)*128+t] = v.x; As[(c+1)*128+t] = v.y;
            As[(c+2)*128+t] = v.z; As[(c+3)*128+t] = v.w;
        }
    } else {
#pragma unroll
        for (int k = 0; k < 64; k++) As[k*128+t] = 0.f;
    }
}

// ---------- P = h@Wd + b1, Q = h@Ws ----------
#define SM_PQ ((8192 + 4096 + 64) * 4)
__global__ void __launch_bounds__(128) k_nodePQ(const float* __restrict__ W1,
                                                const float* __restrict__ b1) {
    extern __shared__ float sm[];
    float* As = sm; float* Ws = sm + 8192; float* b1s = Ws + 4096;
    int t = threadIdx.x, base = blockIdx.x*128, n = base + t;
    load_h_to_As(As, g_h, n, t, n < NN);
    if (t < 64) b1s[t] = b1[t];
    for (int i = t; i < 4096; i += 128) Ws[i] = W1[i];
    __syncthreads();
    int e0 = (t >> 3) * 8, j0 = (t & 7) * 8;
    u64 acc[32];
#pragma unroll
    for (int i = 0; i < 32; i++) acc[i] = 0ull;
    gemm_8x8p(As, Ws, e0, j0, acc);
#pragma unroll
    for (int i = 0; i < 8; i++) {
        int nn = base + e0 + i;
        if (nn < NN) {
            float v[8]; unpack_row(acc + i*4, v);
            float4 o0 = {v[0]+b1s[j0], v[1]+b1s[j0+1], v[2]+b1s[j0+2], v[3]+b1s[j0+3]};
            float4 o1 = {v[4]+b1s[j0+4], v[5]+b1s[j0+5], v[6]+b1s[j0+6], v[7]+b1s[j0+7]};
            *(float4*)(g_P + nn*64 + j0) = o0;
            *(float4*)(g_P + nn*64 + j0 + 4) = o1;
        }
    }
    __syncthreads();
    for (int i = t; i < 4096; i += 128) Ws[i] = W1[4096 + i];
    __syncthreads();
#pragma unroll
    for (int i = 0; i < 32; i++) acc[i] = 0ull;
    gemm_8x8p(As, Ws, e0, j0, acc);
#pragma unroll
    for (int i = 0; i < 8; i++) {
        int nn = base + e0 + i;
        if (nn < NN) {
            float v[8]; unpack_row(acc + i*4, v);
            float4 o0 = {v[0], v[1], v[2], v[3]};
            float4 o1 = {v[4], v[5], v[6], v[7]};
            *(float4*)(g_Q + nn*64 + j0) = o0;
            *(float4*)(g_Q + nn*64 + j0 + 4) = o1;
        }
    }
}

// ---------- pass A: two edges per warp (16 lanes x 4 channels), y1 bf16 + exact stats ----------
__global__ void __launch_bounds__(256) k_edgeA(const int* __restrict__ src, const int* __restrict__ dst,
                                               const float* __restrict__ ea, const float* __restrict__ W1, int slot) {
    __shared__ float Weas[256];
    __shared__ float ssum[64], ssq[64];
    int t = threadIdx.x;
    for (int i = t; i < 256; i += 256) Weas[i] = W1[8192 + i];
    if (t < 64) { ssum[t] = 0.f; ssq[t] = 0.f; }
    __syncthreads();
    int wg = (blockIdx.x*256 + t) >> 5, lane = t & 31;
    int nw = gridDim.x*8;
    int half = lane >> 4, c4 = (lane & 15) * 4;
    u64 wA0 = *(const u64*)(Weas + c4),       wB0 = *(const u64*)(Weas + c4 + 2);
    u64 wA1 = *(const u64*)(Weas + 64 + c4),  wB1 = *(const u64*)(Weas + 64 + c4 + 2);
    u64 wA2 = *(const u64*)(Weas + 128 + c4), wB2 = *(const u64*)(Weas + 128 + c4 + 2);
    u64 wA3 = *(const u64*)(Weas + 192 + c4), wB3 = *(const u64*)(Weas + 192 + c4 + 2);
    u64 spA = 0ull, spB = 0ull, qpA = 0ull, qpB = 0ull;
    for (int eb = wg*2; eb < NE; eb += nw*2) {
        int e = eb + half;
        if (e < NE) {
            int s = src[e], d = dst[e];
            float4 ev = *(const float4*)(ea + e*4);
            ulonglong2 Pv = *(const ulonglong2*)(g_P + d*64 + c4);
            ulonglong2 Qv = *(const ulonglong2*)(g_Q + s*64 + c4);
            u64 e0, e1, e2, e3;
            F2BCAST(e0, ev.x); F2BCAST(e1, ev.y); F2BCAST(e2, ev.z); F2BCAST(e3, ev.w);
            u64 yA; F2ADD(yA, Pv.x, Qv.x);
            F2FMA(yA, e0, wA0); F2FMA(yA, e1, wA1); F2FMA(yA, e2, wA2); F2FMA(yA, e3, wA3);
            u64 yB; F2ADD(yB, Pv.y, Qv.y);
            F2FMA(yB, e0, wB0); F2FMA(yB, e1, wB1); F2FMA(yB, e2, wB2); F2FMA(yB, e3, wB3);
            F2ADD(spA, spA, yA); F2FMA(qpA, yA, yA);
            F2ADD(spB, spB, yB); F2FMA(qpB, yB, yB);
            float a0, a1, b0, b1;
            F2UNPACK(a0, a1, yA); F2UNPACK(b0, b1, yB);
            __nv_bfloat162 h0 = __floats2bfloat162_rn(a0, a1);
            __nv_bfloat162 h1 = __floats2bfloat162_rn(b0, b1);
            uint2 o = { *(unsigned*)&h0, *(unsigned*)&h1 };
            *(uint2*)(g_y1 + (size_t)e*64 + c4) = o;
        }
    }
    float v0, v1, v2, v3, q0, q1, q2, q3;
    F2UNPACK(v0, v1, spA); F2UNPACK(v2, v3, spB);
    F2UNPACK(q0, q1, qpA); F2UNPACK(q2, q3, qpB);
    atomicAdd(&ssum[c4+0], v0); atomicAdd(&ssum[c4+1], v1);
    atomicAdd(&ssum[c4+2], v2); atomicAdd(&ssum[c4+3], v3);
    atomicAdd(&ssq[c4+0], q0); atomicAdd(&ssq[c4+1], q1);
    atomicAdd(&ssq[c4+2], q2); atomicAdd(&ssq[c4+3], q3);
    __syncthreads();
    if (t < 64) { atomicAdd(&g_sum[slot*64+t], ssum[t]); atomicAdd(&g_sq[slot*64+t], ssq[t]); }
}

// ---------- pass B: stream y1, bn1+relu, y2 = m1@W2+b2 (bf16 store), stats2 ----------
#define SM_EB ((8192 + 4096 + 64 + 64 + 64 + 256 + 256) * 4)
__global__ void __launch_bounds__(128) k_edgeB(const float* __restrict__ W2, const float* __restrict__ b2,
                                               const float* __restrict__ g1, const float* __restrict__ be1,
                                               int slot_in, int slot_out) {
    extern __shared__ float sm[];
    float* As = sm; float* Ws = As + 8192;
    float* al = Ws + 4096; float* be = al + 64; float* b2s = be + 64;
    float* ssum = b2s + 64; float* ssq = ssum + 256;
    int t = threadIdx.x, base = blockIdx.x*128, e = base + t;
    for (int i = t; i < 4096; i += 128) Ws[i] = W2[i];
    for (int i = t; i < 256; i += 128) { ssum[i] = 0.f; ssq[i] = 0.f; }
    bnprep(al, be, slot_in, 1.f/NE, g1, be1, t);
    if (t < 64) b2s[t] = b2[t];
    __syncthreads();
    const uint4* yp = (const uint4*)(g_y1 + (size_t)e*64);
#pragma unroll
    for (int q = 0; q < 8; q++) {
        uint4 u = yp[q];
        int c = q*8;
        float2 f0 = __bfloat1622float2(*(__nv_bfloat162*)&u.x);
        float2 f1 = __bfloat1622float2(*(__nv_bfloat162*)&u.y);
        float2 f2 = __bfloat1622float2(*(__nv_bfloat162*)&u.z);
        float2 f3 = __bfloat1622float2(*(__nv_bfloat162*)&u.w);
        As[(c+0)*128+t] = fmaxf(fmaf(al[c+0], f0.x, be[c+0]), 0.f);
        As[(c+1)*128+t] = fmaxf(fmaf(al[c+1], f0.y, be[c+1]), 0.f);
        As[(c+2)*128+t] = fmaxf(fmaf(al[c+2], f1.x, be[c+2]), 0.f);
        As[(c+3)*128+t] = fmaxf(fmaf(al[c+3], f1.y, be[c+3]), 0.f);
        As[(c+4)*128+t] = fmaxf(fmaf(al[c+4], f2.x, be[c+4]), 0.f);
        As[(c+5)*128+t] = fmaxf(fmaf(al[c+5], f2.y, be[c+5]), 0.f);
        As[(c+6)*128+t] = fmaxf(fmaf(al[c+6], f3.x, be[c+6]), 0.f);
        As[(c+7)*128+t] = fmaxf(fmaf(al[c+7], f3.y, be[c+7]), 0.f);
    }
    __syncthreads();
    int e0 = (t >> 3) * 8, j0 = (t & 7) * 8;
    u64 acc[32];
#pragma unroll
    for (int i = 0; i < 32; i++) acc[i] = 0ull;
    gemm_8x8p(As, Ws, e0, j0, acc);
    float cs[8], cq[8];
#pragma unroll
    for (int j = 0; j < 8; j++) { cs[j] = 0.f; cq[j] = 0.f; }
#pragma unroll
    for (int i = 0; i < 8; i++) {
        float v[8]; unpack_row(acc + i*4, v);
#pragma unroll
        for (int j = 0; j < 8; j++) { v[j] += b2s[j0+j]; cs[j] += v[j]; cq[j] += v[j]*v[j]; }
        __nv_bfloat162 p0 = __floats2bfloat162_rn(v[0], v[1]);
        __nv_bfloat162 p1 = __floats2bfloat162_rn(v[2], v[3]);
        __nv_bfloat162 p2 = __floats2bfloat162_rn(v[4], v[5]);
        __nv_bfloat162 p3 = __floats2bfloat162_rn(v[6], v[7]);
        uint4 o;
        o.x = *(unsigned*)&p0; o.y = *(unsigned*)&p1; o.z = *(unsigned*)&p2; o.w = *(unsigned*)&p3;
        *(uint4*)(g_y2 + (size_t)(base+e0+i)*64 + j0) = o;
    }
    int w = t >> 5;
#pragma unroll
    for (int j = 0; j < 8; j++) {
        atomicAdd(&ssum[w*64 + j0 + j], cs[j]);
        atomicAdd(&ssq [w*64 + j0 + j], cq[j]);
    }
    __syncthreads();
    if (t < 64) {
        atomicAdd(&g_sum[slot_out*64+t], ssum[t]+ssum[64+t]+ssum[128+t]+ssum[192+t]);
        atomicAdd(&g_sq [slot_out*64+t], ssq [t]+ssq [64+t]+ssq [128+t]+ssq [192+t]);
    }
}

// ---------- CSR aggregation (bn2+relu fused, bf16 reads) ----------
__global__ void __launch_bounds__(256) k_aggr(const float* __restrict__ g2, const float* __restrict__ be2, int slot) {
    __shared__ float al[64], be[64];
    bnprep(al, be, slot, 1.f/NE, g2, be2, threadIdx.x);
    __syncthreads();
    int w = (blockIdx.x*256 + threadIdx.x) >> 5;
    if (w >= NN) return;
    int lane = threadIdx.x & 31;
    float alA = al[2*lane], beA = be[2*lane];
    float alB = al[2*lane+1], beB = be[2*lane+1];
    const __nv_bfloat162* y = (const __nv_bfloat162*)g_y2;
    float a0 = 0.f, a1 = 0.f;
    int s = g_rowstart[w], e = g_rowstart[w+1];
    for (int p = s; p < e; p++) {
        int eid = g_eidx[p];
        float2 v = __bfloat1622float2(y[eid*32 + lane]);
        a0 += fmaxf(fmaf(alA, v.x, beA), 0.f);
        a1 += fmaxf(fmaf(alB, v.y, beB), 0.f);
    }
    float2 o = {a0, a1};
    *(float2*)(g_aggr + w*64 + 2*lane) = o;
}

// ---------- node update 1 ----------
#define SM_U1 ((8192 + 4096 + 64 + 256 + 256) * 4)
__global__ void __launch_bounds__(128) k_nodeU1(const float* __restrict__ W,
                                                const float* __restrict__ b3, int slot_out) {
    extern __shared__ float sm[];
    float* As = sm; float* Ws = As + 8192; float* b3s = Ws + 4096;
    float* ssum = b3s + 64; float* ssq = ssum + 256;
    int t = threadIdx.x, base = blockIdx.x*128, n = base + t;
    load_h_to_As(As, g_h, n, t, n < NN);
    for (int i = t; i < 4096; i += 128) Ws[i] = W[i];
    if (t < 64) b3s[t] = b3[t];
    for (int i = t; i < 256; i += 128) { ssum[i] = 0.f; ssq[i] = 0.f; }
    __syncthreads();
    int e0 = (t >> 3) * 8, j0 = (t & 7) * 8;
    u64 acc[32];
#pragma unroll
    for (int i = 0; i < 32; i++) acc[i] = 0ull;
    gemm_8x8p(As, Ws, e0, j0, acc);
    __syncthreads();
    load_h_to_As(As, g_aggr, n, t, n < NN);
    for (int i = t; i < 4096; i += 128) Ws[i] = W[4096 + i];
    __syncthreads();
    gemm_8x8p(As, Ws, e0, j0, acc);
    float cs[8], cq[8];
#pragma unroll
    for (int j = 0; j < 8; j++) { cs[j] = 0.f; cq[j] = 0.f; }
#pragma unroll
    for (int i = 0; i < 8; i++) {
        int n2 = base + e0 + i;
        if (n2 < NN) {
            float v[8]; unpack_row(acc + i*4, v);
#pragma unroll
            for (int j = 0; j < 8; j++) { v[j] += b3s[j0+j]; cs[j] += v[j]; cq[j] += v[j]*v[j]; }
            float4 o0 = {v[0],v[1],v[2],v[3]};
            float4 o1 = {v[4],v[5],v[6],v[7]};
            *(float4*)(g_y3 + n2*64 + j0) = o0;
            *(float4*)(g_y3 + n2*64 + j0 + 4) = o1;
        }
    }
    int w = t >> 5;
#pragma unroll
    for (int j = 0; j < 8; j++) {
        atomicAdd(&ssum[w*64 + j0 + j], cs[j]);
        atomicAdd(&ssq [w*64 + j0 + j], cq[j]);
    }
    __syncthreads();
    if (t < 64) {
        atomicAdd(&g_sum[slot_out*64+t], ssum[t]+ssum[64+t]+ssum[128+t]+ssum[192+t]);
        atomicAdd(&g_sq [slot_out*64+t], ssq [t]+ssq [64+t]+ssq [128+t]+ssq [192+t]);
    }
}

// ---------- node update 2 ----------
#define SM_U2 ((8192 + 4096 + 64 + 64 + 64 + 256 + 256) * 4)
__global__ void __launch_bounds__(128) k_nodeU2(const float* __restrict__ W,
                                                const float* __restrict__ b4,
                                                const float* __restrict__ g3, const float* __restrict__ be3,
                                                int slot_in, int slot_out) {
    extern __shared__ float sm[];
    float* As = sm; float* Ws = As + 8192; float* al = Ws + 4096;
    float* be = al + 64; float* b4s = be + 64;
    float* ssum = b4s + 64; float* ssq = ssum + 256;
    int t = threadIdx.x, base = blockIdx.x*128, n = base + t;
    for (int i = t; i < 4096; i += 128) Ws[i] = W[i];
    bnprep(al, be, slot_in, 1.f/NN, g3, be3, t);
    if (t < 64) b4s[t] = b4[t];
    for (int i = t; i < 256; i += 128) { ssum[i] = 0.f; ssq[i] = 0.f; }
    __syncthreads();
    if (n < NN) {
#pragma unroll
        for (int kb = 0; kb < 16; kb++) {
            float4 v = *(const float4*)(g_y3 + n*64 + kb*4);
            int c = kb*4;
            As[(c+0)*128+t] = fmaxf(fmaf(al[c+0], v.x, be[c+0]), 0.f);
            As[(c+1)*128+t] = fmaxf(fmaf(al[c+1], v.y, be[c+1]), 0.f);
            As[(c+2)*128+t] = fmaxf(fmaf(al[c+2], v.z, be[c+2]), 0.f);
            As[(c+3)*128+t] = fmaxf(fmaf(al[c+3], v.w, be[c+3]), 0.f);
        }
    } else {
#pragma unroll
        for (int k = 0; k < 64; k++) As[k*128+t] = 0.f;
    }
    __syncthreads();
    int e0 = (t >> 3) * 8, j0 = (t & 7) * 8;
    u64 acc[32];
#pragma unroll
    for (int i = 0; i < 32; i++) acc[i] = 0ull;
    gemm_8x8p(As, Ws, e0, j0, acc);
    float cs[8], cq[8];
#pragma unroll
    for (int j = 0; j < 8; j++) { cs[j] = 0.f; cq[j] = 0.f; }
#pragma unroll
    for (int i = 0; i < 8; i++) {
        int n2 = base + e0 + i;
        if (n2 < NN) {
            float v[8]; unpack_row(acc + i*4, v);
#pragma unroll
            for (int j = 0; j < 8; j++) { v[j] += b4s[j0+j]; cs[j] += v[j]; cq[j] += v[j]*v[j]; }
            float4 o0 = {v[0],v[1],v[2],v[3]};
            float4 o1 = {v[4],v[5],v[6],v[7]};
            *(float4*)(g_y4 + n2*64 + j0) = o0;
            *(float4*)(g_y4 + n2*64 + j0 + 4) = o1;
        }
    }
    int w = t >> 5;
#pragma unroll
    for (int j = 0; j < 8; j++) {
        atomicAdd(&ssum[w*64 + j0 + j], cs[j]);
        atomicAdd(&ssq [w*64 + j0 + j], cq[j]);
    }
    __syncthreads();
    if (t < 64) {
        atomicAdd(&g_sum[slot_out*64+t], ssum[t]+ssum[64+t]+ssum[128+t]+ssum[192+t]);
        atomicAdd(&g_sq [slot_out*64+t], ssq [t]+ssq [64+t]+ssq [128+t]+ssq [192+t]);
    }
}

// ---------- residual (bn4+relu fused) ----------
__global__ void __launch_bounds__(256) k_resid(const float* __restrict__ g4, const float* __restrict__ be4, int slot) {
    __shared__ float al[64], be[64];
    bnprep(al, be, slot, 1.f/NN, g4, be4, threadIdx.x);
    __syncthreads();
    int i = blockIdx.x*256 + threadIdx.x;
    if (i < NN*D) {
        int c = i & 63;
        g_h[i] += fmaxf(fmaf(al[c], g_y4[i], be[c]), 0.f);
    }
}

// ---------- pooling ----------
__global__ void k_pool(const int* __restrict__ batch) {
    int w = blockIdx.x*8 + (threadIdx.x >> 5);
    int lane = threadIdx.x & 31;
    int n0 = w*64, n1 = min(n0 + 64, NN);
    if (n0 >= NN) return;
    float ax = 0.f, ay = 0.f, cnt = 0.f;
    int curg = batch[n0];
    for (int n = n0; n < n1; n++) {
        int g = batch[n];
        if (g != curg) {
            atomicAdd(&g_gsum[curg*64 + 2*lane], ax);
            atomicAdd(&g_gsum[curg*64 + 2*lane + 1], ay);
            if (lane == 0) atomicAdd(&g_gcnt[curg], cnt);
            ax = 0.f; ay = 0.f; cnt = 0.f; curg = g;
        }
        float2 v = *(const float2*)(g_h + n*64 + 2*lane);
        ax += v.x; ay += v.y; cnt += 1.f;
    }
    atomicAdd(&g_gsum[curg*64 + 2*lane], ax);
    atomicAdd(&g_gsum[curg*64 + 2*lane + 1], ay);
    if (lane == 0) atomicAdd(&g_gcnt[curg], cnt);
}

__global__ void k_pred(const float* __restrict__ pW, const float* __restrict__ pb,
                       float* __restrict__ out) {
    int g = threadIdx.x;
    if (g < NG) {
        float cnt = fmaxf(g_gcnt[g], 1.f);
        float acc = pb[0];
        for (int c = 0; c < D; c++) acc += g_gsum[g*64 + c] / cnt * pW[c];
        out[g] = acc;
    }
}

extern "C" void kernel_launch(void* const* d_in, const int* in_sizes, int n_in,
                              void* d_out, int out_size) {
    const float* x    = (const float*)d_in[0];
    const float* ea   = (const float*)d_in[1];
    const int*   ei   = (const int*)d_in[2];
    const int*   batch= (const int*)d_in[3];
    const float* linW = (const float*)d_in[4];
    const float* linb = (const float*)d_in[5];
    const float* mW1  = (const float*)d_in[6];
    const float* mb1  = (const float*)d_in[7];
    const float* mg1  = (const float*)d_in[8];
    const float* mbe1 = (const float*)d_in[9];
    const float* mW2  = (const float*)d_in[10];
    const float* mb2  = (const float*)d_in[11];
    const float* mg2  = (const float*)d_in[12];
    const float* mbe2 = (const float*)d_in[13];
    const float* uW1  = (const float*)d_in[14];
    const float* ub1  = (const float*)d_in[15];
    const float* ug1  = (const float*)d_in[16];
    const float* ube1 = (const float*)d_in[17];
    const float* uW2  = (const float*)d_in[18];
    const float* ub2  = (const float*)d_in[19];
    const float* ug2  = (const float*)d_in[20];
    const float* ube2 = (const float*)d_in[21];
    const float* pW   = (const float*)d_in[22];
    const float* pb   = (const float*)d_in[23];
    float* out = (float*)d_out;
    const int* src = ei;
    const int* dst = ei + NE;

    cudaFuncSetAttribute(k_nodePQ, cudaFuncAttributeMaxDynamicSharedMemorySize, SM_PQ);
    cudaFuncSetAttribute(k_edgeB,  cudaFuncAttributeMaxDynamicSharedMemorySize, SM_EB);
    cudaFuncSetAttribute(k_nodeU1, cudaFuncAttributeMaxDynamicSharedMemorySize, SM_U1);
    cudaFuncSetAttribute(k_nodeU2, cudaFuncAttributeMaxDynamicSharedMemorySize, SM_U2);

    int nblk = (NN + 127) / 128;

    // order chosen so the ncu window (4th launch) hits k_edgeA
    k_lin_in<<<(NN*4+255)/256, 256>>>(x, linW, linb);
    k_zero<<<(NN+255)/256, 256>>>();
    k_nodePQ<<<nblk, 128, SM_PQ>>>(mW1, mb1);
    k_edgeA<<<592, 256>>>(src, dst, ea, mW1, 0);
    k_edgeB<<<NE/128, 128, SM_EB>>>(mW2, mb2, mg1, mbe1, 0, 1);
    k_hist<<<(NE+255)/256, 256>>>(dst);
    k_scan<<<1, 1024>>>();
    k_scatter<<<(NE+255)/256, 256>>>(dst);

    for (int l = 0; l < 4; l++) {
        const float* W1 = mW1 + l*132*64;
        int s0 = l*4;
        if (l > 0) {
            k_nodePQ<<<nblk, 128, SM_PQ>>>(W1, mb1 + l*64);
            k_edgeA<<<592, 256>>>(src, dst, ea, W1, s0);
            k_edgeB<<<NE/128, 128, SM_EB>>>(mW2 + l*4096, mb2 + l*64,
                                            mg1 + l*64, mbe1 + l*64, s0, s0+1);
        }
        k_aggr<<<(NN*32+255)/256, 256>>>(mg2 + l*64, mbe2 + l*64, s0+1);
        k_nodeU1<<<nblk, 128, SM_U1>>>(uW1 + l*128*64, ub1 + l*64, s0+2);
        k_nodeU2<<<nblk, 128, SM_U2>>>(uW2 + l*4096, ub2 + l*64,
                                       ug1 + l*64, ube1 + l*64, s0+2, s0+3);
        k_resid<<<(NN*D+255)/256, 256>>>(ug2 + l*64, ube2 + l*64, s0+3);
    }
    k_pool<<<98, 256>>>(batch);
    k_pred<<<1, 32>>>(pW, pb, out);
}